// round 8
// baseline (speedup 1.0000x reference)
#include <cuda_runtime.h>
#include <cuda_fp16.h>
#include <cstdint>

#define BD 2
#define HD 64
#define WD 64
#define CD 256
#define GD 8
#define KP 9
#define HCD 32
#define PD (HD*WD)
#define C3 (3*CD)        // 768
#define NOP 192          // padded offset/mask outputs (153 real)
#define NF 768
#define MR (BD*PD)       // 8192

// ---------------- scratch (device globals; no allocation) ----------------
__device__ float  g_qkv[MR*C3];          // after qkv GEMM
__device__ float  g_q[MR*CD];            // q after dwconv (fp32)
__device__ __half g_kvh[MR*CD*2];        // {k,v} fp16 interleaved after dwconv
__device__ float  g_offmask[MR*NOP];
__device__ float  g_combB[NOP];
__device__ __half g_xhi[MR*CD], g_xlo[MR*CD];
__device__ __half g_qwh[C3*CD], g_qwl[C3*CD];      // qkv_w^T hi/lo
__device__ __half g_pwh[CD*CD], g_pwl[CD*CD];      // proj_w^T hi/lo
__device__ __half g_cwh[NOP*NF], g_cwl[NOP*NF];    // combW^T hi/lo
__device__ __half g_fh[MR*NF], g_fl[MR*NF];        // im2col features
__device__ __half g_aoh[MR*CD], g_aol[MR*CD];      // attention out

__constant__ float c_PTS[18] = {-1,-1,-1,0,-1,1,0,-1,0,0,0,1,1,-1,1,0,1,1};

// ---------------- helpers ----------------
__device__ __forceinline__ uint32_t smem_u32(const void* p) {
    uint32_t a;
    asm("{ .reg .u64 t; cvta.to.shared.u64 t, %1; cvt.u32.u64 %0, t; }" : "=r"(a) : "l"(p));
    return a;
}
__device__ __forceinline__ void cp16(uint32_t dst, const void* src) {
    asm volatile("cp.async.cg.shared.global [%0], [%1], 16;" :: "r"(dst), "l"(src));
}
#define CP_COMMIT() asm volatile("cp.async.commit_group;" ::: "memory")
#define CP_WAIT0()  asm volatile("cp.async.wait_group 0;" ::: "memory")
#define CP_WAIT1()  asm volatile("cp.async.wait_group 1;" ::: "memory")
#define LDSM_X4(r, a) asm volatile( \
    "ldmatrix.sync.aligned.m8n8.x4.shared.b16 {%0,%1,%2,%3}, [%4];" \
    : "=r"((r)[0]),"=r"((r)[1]),"=r"((r)[2]),"=r"((r)[3]) : "r"(a))
#define LDSM_X2(r, a) asm volatile( \
    "ldmatrix.sync.aligned.m8n8.x2.shared.b16 {%0,%1}, [%2];" \
    : "=r"((r)[0]),"=r"((r)[1]) : "r"(a))
#define MMA16816(c, a, b) asm volatile( \
    "mma.sync.aligned.m16n8k16.row.col.f32.f16.f16.f32 " \
    "{%0,%1,%2,%3}, {%4,%5,%6,%7}, {%8,%9}, {%0,%1,%2,%3};" \
    : "+f"((c)[0]),"+f"((c)[1]),"+f"((c)[2]),"+f"((c)[3]) \
    : "r"((a)[0]),"r"((a)[1]),"r"((a)[2]),"r"((a)[3]), "r"((b)[0]),"r"((b)[1]))

__device__ __forceinline__ void split1(float v, __half& hi, __half& lo) {
    hi = __float2half_rn(v);
    lo = __float2half_rn(v - __half2float(hi));
}

// ============ split-fp16 tensor-core GEMM, double-buffered ============
#define A_OFF(s,r,c) ((s)*128*40 + (r)*40 + (c))
#define B_OFF(s,r,c) ((s)*64*40 + (r)*40 + (c))
#define GEMM_SMEM (2*(2*128*40 + 2*64*40) * 2)   // 61440 bytes

__global__ void __launch_bounds__(256, 2) gemm_kernel(
    const __half* __restrict__ Ah, const __half* __restrict__ Al,
    const __half* __restrict__ Bh, const __half* __restrict__ Bl,
    const float* __restrict__ bias, float* __restrict__ C, int N, int K)
{
    extern __shared__ __half sm[];
    __half* sAh = sm;
    __half* sAl = sAh + 2*128*40;
    __half* sBh = sAl + 2*128*40;
    __half* sBl = sBh + 2*64*40;

    int tid = threadIdx.x;
    int warp = tid >> 5, lane = tid & 31;
    int wm = warp >> 1, wn = warp & 1;
    int row0 = blockIdx.y * 128, col0 = blockIdx.x * 64;

    float acc[2][4][4];
#pragma unroll
    for (int mi = 0; mi < 2; mi++)
#pragma unroll
        for (int j = 0; j < 4; j++)
#pragma unroll
            for (int r = 0; r < 4; r++) acc[mi][j][r] = 0.f;

#define STAGE(kc, s) do { \
    int k0 = (kc) << 5; \
    _Pragma("unroll") \
    for (int i = 0; i < 2; i++) { \
        int e = tid + i * 256; \
        int r = e >> 2, cs = (e & 3) * 8; \
        size_t ga = (size_t)(row0 + r) * K + k0 + cs; \
        cp16(smem_u32(&sAh[A_OFF(s, r, cs)]), Ah + ga); \
        cp16(smem_u32(&sAl[A_OFF(s, r, cs)]), Al + ga); \
    } \
    { int r = tid >> 2, cs = (tid & 3) * 8; \
      size_t gb = (size_t)(col0 + r) * K + k0 + cs; \
      cp16(smem_u32(&sBh[B_OFF(s, r, cs)]), Bh + gb); \
      cp16(smem_u32(&sBl[B_OFF(s, r, cs)]), Bl + gb); } \
} while (0)

    int nk = K >> 5;
    STAGE(0, 0);
    CP_COMMIT();
    for (int kc = 0; kc < nk; kc++) {
        int cur = kc & 1;
        if (kc + 1 < nk) { STAGE(kc + 1, cur ^ 1); CP_COMMIT(); CP_WAIT1(); }
        else             { CP_WAIT0(); }
        __syncthreads();

#pragma unroll
        for (int ks = 0; ks < 2; ks++) {
            uint32_t aH[2][4], aL[2][4], bH[4][2], bL[4][2];
#pragma unroll
            for (int mi = 0; mi < 2; mi++) {
                int rowa = wm * 32 + mi * 16 + (lane & 15);
                int cola = ks * 16 + (lane >> 4) * 8;
                LDSM_X4(aH[mi], smem_u32(&sAh[A_OFF(cur, rowa, cola)]));
                LDSM_X4(aL[mi], smem_u32(&sAl[A_OFF(cur, rowa, cola)]));
            }
#pragma unroll
            for (int j = 0; j < 4; j++) {
                int l16 = lane & 15;
                int rowb = wn * 32 + j * 8 + (l16 & 7);
                int colb = ks * 16 + ((l16 >> 3) & 1) * 8;
                LDSM_X2(bH[j], smem_u32(&sBh[B_OFF(cur, rowb, colb)]));
                LDSM_X2(bL[j], smem_u32(&sBl[B_OFF(cur, rowb, colb)]));
            }
#pragma unroll
            for (int mi = 0; mi < 2; mi++)
#pragma unroll
                for (int j = 0; j < 4; j++) {
                    MMA16816(acc[mi][j], aH[mi], bH[j]);
                    MMA16816(acc[mi][j], aH[mi], bL[j]);
                    MMA16816(acc[mi][j], aL[mi], bH[j]);
                }
        }
        __syncthreads();
    }
#undef STAGE

    int g = lane >> 2, t = lane & 3;
#pragma unroll
    for (int mi = 0; mi < 2; mi++)
#pragma unroll
        for (int j = 0; j < 4; j++) {
            int col = col0 + wn * 32 + j * 8 + t * 2;
            float2 bv = *reinterpret_cast<const float2*>(&bias[col]);
            int r0 = row0 + wm * 32 + mi * 16 + g;
            float2 o0 = make_float2(acc[mi][j][0] + bv.x, acc[mi][j][1] + bv.y);
            float2 o1 = make_float2(acc[mi][j][2] + bv.x, acc[mi][j][3] + bv.y);
            *reinterpret_cast<float2*>(&C[(size_t)r0 * N + col]) = o0;
            *reinterpret_cast<float2*>(&C[(size_t)(r0 + 8) * N + col]) = o1;
        }
}

// ------- merged conversions -------
__global__ void __launch_bounds__(256) convert_all_kernel(
    const float* __restrict__ x, const float* __restrict__ qkv_w,
    const float* __restrict__ proj_w)
{
    int bid = blockIdx.x, tid = threadIdx.x;
    if (bid < 2048) {
        int i = (bid * 256 + tid) * 4;
        float4 v = *reinterpret_cast<const float4*>(&x[i]);
        float f[4] = {v.x, v.y, v.z, v.w};
#pragma unroll
        for (int j = 0; j < 4; j++) {
            __half h, l; split1(f[j], h, l);
            g_xhi[i + j] = h; g_xlo[i + j] = l;
        }
    } else if (bid < 2048 + C3) {
        int o = bid - 2048;
        __half h, l; split1(qkv_w[(size_t)tid * C3 + o], h, l);
        g_qwh[(size_t)o * CD + tid] = h;
        g_qwl[(size_t)o * CD + tid] = l;
    } else {
        int o = bid - 2048 - C3;
        __half h, l; split1(proj_w[(size_t)tid * CD + o], h, l);
        g_pwh[(size_t)o * CD + tid] = h;
        g_pwl[(size_t)o * CD + tid] = l;
    }
}

// ---------------- depthwise 3x3, 4 px/thread; q fp32, kv fp16 pair --------
__global__ void __launch_bounds__(192) dwconv_kernel(
    const float* __restrict__ in, const float* __restrict__ w,
    const float* __restrict__ bias)
{
    int c = threadIdx.x * 4;
    int x0 = blockIdx.x * 4, y = blockIdx.y, b = blockIdx.z;
    float4 bz = *reinterpret_cast<const float4*>(&bias[c]);
    float4 acc[4] = {bz, bz, bz, bz};
#pragma unroll
    for (int ky = 0; ky < 3; ky++) {
        int yy = y + ky - 1;
        if (yy < 0 || yy >= HD) continue;
        const float* rowp = in + ((size_t)(b * HD + yy) * WD) * C3 + c;
        float4 iv[6];
#pragma unroll
        for (int j = 0; j < 6; j++) {
            int xx = x0 - 1 + j;
            iv[j] = (xx >= 0 && xx < WD)
                ? *reinterpret_cast<const float4*>(rowp + (size_t)xx * C3)
                : make_float4(0.f, 0.f, 0.f, 0.f);
        }
#pragma unroll
        for (int kx = 0; kx < 3; kx++) {
            float4 wv = *reinterpret_cast<const float4*>(&w[(ky * 3 + kx) * C3 + c]);
#pragma unroll
            for (int p = 0; p < 4; p++) {
                acc[p].x += wv.x * iv[p + kx].x; acc[p].y += wv.y * iv[p + kx].y;
                acc[p].z += wv.z * iv[p + kx].z; acc[p].w += wv.w * iv[p + kx].w;
            }
        }
    }
#pragma unroll
    for (int p = 0; p < 4; p++) {
        size_t pix = (size_t)(b * HD + y) * WD + x0 + p;
        if (c < CD) {
            *reinterpret_cast<float4*>(&g_q[pix * CD + c]) = acc[p];
        } else if (c < 2 * CD) {          // k -> even half slots
            __half* bp = g_kvh + (pix * CD + (c - CD)) * 2;
            bp[0] = __float2half_rn(acc[p].x); bp[2] = __float2half_rn(acc[p].y);
            bp[4] = __float2half_rn(acc[p].z); bp[6] = __float2half_rn(acc[p].w);
        } else {                           // v -> odd half slots
            __half* bp = g_kvh + (pix * CD + (c - 2 * CD)) * 2 + 1;
            bp[0] = __float2half_rn(acc[p].x); bp[2] = __float2half_rn(acc[p].y);
            bp[4] = __float2half_rn(acc[p].z); bp[6] = __float2half_rn(acc[p].w);
        }
    }
}

// ---------------- fold pconv+proj -> combW^T hi/lo + bias ----------------
__global__ void __launch_bounds__(128) prep_kernel(
    const float* __restrict__ off_pconv_w, const float* __restrict__ off_w,
    const float* __restrict__ off_b, const float* __restrict__ mask_pconv_w,
    const float* __restrict__ mask_w, const float* __restrict__ mask_b)
{
    int o = blockIdx.x;
    int f = blockIdx.y * 128 + threadIdx.x;
    if (o >= 153) {
        g_cwh[(size_t)o * NF + f] = __float2half_rn(0.f);
        g_cwl[(size_t)o * NF + f] = __float2half_rn(0.f);
        if (threadIdx.x == 0 && blockIdx.y == 0) g_combB[o] = 0.f;
        return;
    }
    bool is_mask = (o >= 144);
    int g = 0, j = 0, kk = 0;
    if (!is_mask) { g = o / 18; j = o % 18; } else { kk = o - 144; }

    float s;
    if (f < 576) {
        int t = f >> 6, ic = f & 63;
        s = 0.f;
        if (!is_mask) {
            const float* ow = off_w + (g * 18 + j) * 256;
            const float* pc = off_pconv_w + ((size_t)(g * 64) * 64 + ic) * 9 + t;
#pragma unroll 4
            for (int oc = 0; oc < 64; oc++) s += ow[oc] * pc[(size_t)oc * 64 * 9];
        } else {
            const float* mw = mask_w + kk * 256;
            const float* pc = mask_pconv_w + (size_t)ic * 9 + t;
#pragma unroll 4
            for (int oc = 0; oc < 64; oc++) s += mw[oc] * pc[(size_t)oc * 64 * 9];
        }
    } else {
        int ch = f - 512;
        s = is_mask ? mask_w[kk * 256 + ch] : off_w[(g * 18 + j) * 256 + ch];
    }
    __half h, l; split1(s, h, l);
    g_cwh[(size_t)o * NF + f] = h;
    g_cwl[(size_t)o * NF + f] = l;
    if (threadIdx.x == 0 && blockIdx.y == 0)
        g_combB[o] = is_mask ? mask_b[kk]
                             : (off_b[g * 18 + j] + c_PTS[j] * (float)(2 * g + 1));
}

// ---------------- im2col feature matrix from g_q, hi/lo fp16 -------------
__global__ void __launch_bounds__(256) im2col_kernel()
{
    int bh = blockIdx.x;
    int b = bh >> 6, h = bh & 63;
    int tid = threadIdx.x;
#pragma unroll
    for (int t = 0; t < 9; t++) {
        int yy = h + t / 3 - 1;
        int dx = t % 3 - 1;
        bool rowok = (yy >= 0 && yy < HD);
        const float* rowp = g_q + (size_t)(b * HD + yy) * WD * CD;
#pragma unroll
        for (int it = 0; it < 4; it++) {
            int e = tid + it * 256;
            int px = e >> 4, c4 = (e & 15) << 2;
            int xx = px + dx;
            float4 v = make_float4(0.f, 0.f, 0.f, 0.f);
            if (rowok && xx >= 0 && xx < WD)
                v = *reinterpret_cast<const float4*>(rowp + (size_t)xx * CD + c4);
            size_t oo = (size_t)(bh * 64 + px) * NF + t * 64 + c4;
            __half h0,h1,h2,h3,l0,l1,l2,l3;
            split1(v.x,h0,l0); split1(v.y,h1,l1); split1(v.z,h2,l2); split1(v.w,h3,l3);
            *reinterpret_cast<__half2*>(&g_fh[oo])   = __halves2half2(h0,h1);
            *reinterpret_cast<__half2*>(&g_fh[oo+2]) = __halves2half2(h2,h3);
            *reinterpret_cast<__half2*>(&g_fl[oo])   = __halves2half2(l0,l1);
            *reinterpret_cast<__half2*>(&g_fl[oo+2]) = __halves2half2(l2,l3);
        }
    }
    const float* crow = g_q + (size_t)(b * HD + h) * WD * CD;
#pragma unroll
    for (int it = 0; it < 12; it++) {
        int e = tid + it * 256;
        int px = e / 48, c4 = (e % 48) << 2;
        float4 v = *reinterpret_cast<const float4*>(crow + (size_t)px * CD + 64 + c4);
        size_t oo = (size_t)(bh * 64 + px) * NF + 576 + c4;
        __half h0,h1,h2,h3,l0,l1,l2,l3;
        split1(v.x,h0,l0); split1(v.y,h1,l1); split1(v.z,h2,l2); split1(v.w,h3,l3);
        *reinterpret_cast<__half2*>(&g_fh[oo])   = __halves2half2(h0,h1);
        *reinterpret_cast<__half2*>(&g_fh[oo+2]) = __halves2half2(h2,h3);
        *reinterpret_cast<__half2*>(&g_fl[oo])   = __halves2half2(l0,l1);
        *reinterpret_cast<__half2*>(&g_fl[oo+2]) = __halves2half2(l2,l3);
    }
}

// ---------------- deformable attention: warp per (b,g,pixel) --------------
__global__ void __launch_bounds__(256) attn_kernel()
{
    int warp = threadIdx.x >> 5, lane = threadIdx.x & 31;
    int px = blockIdx.x * 8 + warp;
    int g = blockIdx.y, b = blockIdx.z;
    int h = px >> 6, w = px & 63;

    const __half2* kvp = reinterpret_cast<const __half2*>(g_kvh);
    const float* om = g_offmask + ((size_t)(b * HD + h) * WD + w) * NOP;
    float qv = g_q[((size_t)(b * HD + h) * WD + w) * CD + g * HCD + lane]
             * 0.17677669529663687f;

    float attn[KP], vk[KP];
#pragma unroll
    for (int k = 0; k < KP; k++) {
        float ox = om[g * 18 + 2 * k], oy = om[g * 18 + 2 * k + 1], mk = om[144 + k];
        float cx = fminf(fmaxf((float)w + ox, 0.f), (float)(WD - 1));
        float cy = fminf(fmaxf((float)h + oy, 0.f), (float)(HD - 1));
        float x0f = floorf(cx), y0f = floorf(cy);
        float fx = cx - x0f, fy = cy - y0f;
        int x0 = (int)x0f, y0 = (int)y0f;
        int x1 = min(x0 + 1, WD - 1), y1 = min(y0 + 1, HD - 1);
        size_t i00 = ((size_t)(b * HD + y0) * WD + x0) * CD + g * HCD + lane;
        size_t i01 = ((size_t)(b * HD + y0) * WD + x1) * CD + g * HCD + lane;
        size_t i10 = ((size_t)(b * HD + y1) * WD + x0) * CD + g * HCD + lane;
        size_t i11 = ((size_t)(b * HD + y1) * WD + x1) * CD + g * HCD + lane;
        float2 kv00 = __half22float2(kvp[i00]);
        float2 kv01 = __half22float2(kvp[i01]);
        float2 kv10 = __half22float2(kvp[i10]);
        float2 kv11 = __half22float2(kvp[i11]);
        float w00 = (1.f - fx) * (1.f - fy), w01 = fx * (1.f - fy);
        float w10 = (1.f - fx) * fy,         w11 = fx * fy;
        float kvv = kv00.x*w00 + kv01.x*w01 + kv10.x*w10 + kv11.x*w11;
        float vvv = kv00.y*w00 + kv01.y*w01 + kv10.y*w10 + kv11.y*w11;
        kvv *= mk; vvv *= mk;
        float d = qv * kvv;
#pragma unroll
        for (int s = 16; s; s >>= 1) d += __shfl_xor_sync(0xffffffffu, d, s);
        attn[k] = d;
        vk[k] = vvv;
    }
    float m = attn[0];
#pragma unroll
    for (int k = 1; k < KP; k++) m = fmaxf(m, attn[k]);
    float ssum = 0.f, o = 0.f;
#pragma unroll
    for (int k = 0; k < KP; k++) {
        float e = __expf(attn[k] - m);
        ssum += e;
        o += e * vk[k];
    }
    o /= ssum;
    size_t oi = ((size_t)((b * HD + h) * WD + w)) * CD + g * HCD + lane;
    __half hh, ll; split1(o, hh, ll);
    g_aoh[oi] = hh; g_aol[oi] = ll;
}

// --------------------------------- launch ---------------------------------
extern "C" void kernel_launch(void* const* d_in, const int* in_sizes, int n_in,
                              void* d_out, int out_size)
{
    const float* x            = (const float*)d_in[0];
    const float* qkv_w        = (const float*)d_in[1];
    const float* qkv_b        = (const float*)d_in[2];
    const float* dw_w         = (const float*)d_in[3];
    const float* dw_b         = (const float*)d_in[4];
    const float* off_pconv_w  = (const float*)d_in[5];
    const float* off_w        = (const float*)d_in[6];
    const float* off_b        = (const float*)d_in[7];
    const float* mask_pconv_w = (const float*)d_in[8];
    const float* mask_w       = (const float*)d_in[9];
    const float* mask_b       = (const float*)d_in[10];
    const float* proj_w       = (const float*)d_in[11];
    const float* proj_b       = (const float*)d_in[12];
    float* out = (float*)d_out;

    cudaFuncSetAttribute(gemm_kernel,
                         cudaFuncAttributeMaxDynamicSharedMemorySize, GEMM_SMEM);

    __half *xh, *xl, *qwh, *qwl, *pwh, *pwl, *cwh, *cwl, *fh, *fl, *aoh, *aol;
    float *qkv, *combB, *offmask;
    cudaGetSymbolAddress((void**)&xh, g_xhi);   cudaGetSymbolAddress((void**)&xl, g_xlo);
    cudaGetSymbolAddress((void**)&qwh, g_qwh);  cudaGetSymbolAddress((void**)&qwl, g_qwl);
    cudaGetSymbolAddress((void**)&pwh, g_pwh);  cudaGetSymbolAddress((void**)&pwl, g_pwl);
    cudaGetSymbolAddress((void**)&cwh, g_cwh);  cudaGetSymbolAddress((void**)&cwl, g_cwl);
    cudaGetSymbolAddress((void**)&fh, g_fh);    cudaGetSymbolAddress((void**)&fl, g_fl);
    cudaGetSymbolAddress((void**)&aoh, g_aoh);  cudaGetSymbolAddress((void**)&aol, g_aol);
    cudaGetSymbolAddress((void**)&qkv, g_qkv);
    cudaGetSymbolAddress((void**)&combB, g_combB);
    cudaGetSymbolAddress((void**)&offmask, g_offmask);

    convert_all_kernel<<<2048 + C3 + CD, 256>>>(x, qkv_w, proj_w);
    {
        dim3 grid(NOP, NF / 128);
        prep_kernel<<<grid, 128>>>(off_pconv_w, off_w, off_b,
                                   mask_pconv_w, mask_w, mask_b);
    }
    {
        dim3 grid(C3 / 64, MR / 128);
        gemm_kernel<<<grid, 256, GEMM_SMEM>>>(xh, xl, qwh, qwl, qkv_b, qkv, C3, CD);
    }
    {
        dim3 grid(WD / 4, HD, BD);
        dwconv_kernel<<<grid, 192>>>(qkv, dw_w, dw_b);
    }
    im2col_kernel<<<BD * HD, 256>>>();
    {
        dim3 grid(NOP / 64, MR / 128);
        gemm_kernel<<<grid, 256, GEMM_SMEM>>>(fh, fl, cwh, cwl, combB, offmask, NOP, NF);
    }
    {
        dim3 grid(PD / 8, GD, BD);
        attn_kernel<<<grid, 256>>>();
    }
    {
        dim3 grid(CD / 64, MR / 128);
        gemm_kernel<<<grid, 256, GEMM_SMEM>>>(aoh, aol, pwh, pwl, proj_b, out, CD, CD);
    }
}

// round 9
// speedup vs baseline: 1.0099x; 1.0099x over previous
#include <cuda_runtime.h>
#include <cuda_fp16.h>
#include <cstdint>

#define BD 2
#define HD 64
#define WD 64
#define CD 256
#define GD 8
#define KP 9
#define HCD 32
#define PD (HD*WD)
#define C3 (3*CD)        // 768
#define NOP 192          // padded offset/mask outputs (153 real)
#define NF 768
#define MR (BD*PD)       // 8192

// ---------------- scratch (device globals; no allocation) ----------------
__device__ float  g_qkv[MR*C3];          // after qkv GEMM
__device__ float  g_q[MR*CD];            // q after dwconv (fp32)
__device__ float2 g_kv[MR*CD];           // {k,v} fp32 interleaved after dwconv
__device__ float  g_offmask[MR*NOP];
__device__ float  g_combB[NOP];
__device__ __half g_xhi[MR*CD], g_xlo[MR*CD];
__device__ __half g_qwh[C3*CD], g_qwl[C3*CD];      // qkv_w^T hi/lo
__device__ __half g_pwh[CD*CD], g_pwl[CD*CD];      // proj_w^T hi/lo
__device__ __half g_cwh[NOP*NF], g_cwl[NOP*NF];    // combW^T hi/lo
__device__ __half g_fh[MR*NF], g_fl[MR*NF];        // im2col features
__device__ __half g_aoh[MR*CD], g_aol[MR*CD];      // attention out

__constant__ float c_PTS[18] = {-1,-1,-1,0,-1,1,0,-1,0,0,0,1,1,-1,1,0,1,1};

// ---------------- helpers ----------------
__device__ __forceinline__ uint32_t smem_u32(const void* p) {
    uint32_t a;
    asm("{ .reg .u64 t; cvta.to.shared.u64 t, %1; cvt.u32.u64 %0, t; }" : "=r"(a) : "l"(p));
    return a;
}
__device__ __forceinline__ void cp16(uint32_t dst, const void* src) {
    asm volatile("cp.async.cg.shared.global [%0], [%1], 16;" :: "r"(dst), "l"(src));
}
#define CP_COMMIT() asm volatile("cp.async.commit_group;" ::: "memory")
#define CP_WAIT0()  asm volatile("cp.async.wait_group 0;" ::: "memory")
#define CP_WAIT1()  asm volatile("cp.async.wait_group 1;" ::: "memory")
#define LDSM_X4(r, a) asm volatile( \
    "ldmatrix.sync.aligned.m8n8.x4.shared.b16 {%0,%1,%2,%3}, [%4];" \
    : "=r"((r)[0]),"=r"((r)[1]),"=r"((r)[2]),"=r"((r)[3]) : "r"(a))
#define LDSM_X2(r, a) asm volatile( \
    "ldmatrix.sync.aligned.m8n8.x2.shared.b16 {%0,%1}, [%2];" \
    : "=r"((r)[0]),"=r"((r)[1]) : "r"(a))
#define MMA16816(c, a, b) asm volatile( \
    "mma.sync.aligned.m16n8k16.row.col.f32.f16.f16.f32 " \
    "{%0,%1,%2,%3}, {%4,%5,%6,%7}, {%8,%9}, {%0,%1,%2,%3};" \
    : "+f"((c)[0]),"+f"((c)[1]),"+f"((c)[2]),"+f"((c)[3]) \
    : "r"((a)[0]),"r"((a)[1]),"r"((a)[2]),"r"((a)[3]), "r"((b)[0]),"r"((b)[1]))

__device__ __forceinline__ void split1(float v, __half& hi, __half& lo) {
    hi = __float2half_rn(v);
    lo = __float2half_rn(v - __half2float(hi));
}

// ============ split-fp16 tensor-core GEMM, double-buffered ============
// C[M,N] = A·B^T + bias. Columns < n3 get the full 3-product split
// (AhBh+AhBl+AlBh); columns >= n3 get 2 products (drop AlBh).
#define A_OFF(s,r,c) ((s)*128*40 + (r)*40 + (c))
#define B_OFF(s,r,c) ((s)*64*40 + (r)*40 + (c))
#define GEMM_SMEM (2*(2*128*40 + 2*64*40) * 2)   // 61440 bytes

__global__ void __launch_bounds__(256, 2) gemm_kernel(
    const __half* __restrict__ Ah, const __half* __restrict__ Al,
    const __half* __restrict__ Bh, const __half* __restrict__ Bl,
    const float* __restrict__ bias, float* __restrict__ C, int N, int K, int n3)
{
    extern __shared__ __half sm[];
    __half* sAh = sm;
    __half* sAl = sAh + 2*128*40;
    __half* sBh = sAl + 2*128*40;
    __half* sBl = sBh + 2*64*40;

    int tid = threadIdx.x;
    int warp = tid >> 5, lane = tid & 31;
    int wm = warp >> 1, wn = warp & 1;
    int row0 = blockIdx.y * 128, col0 = blockIdx.x * 64;
    bool full3 = (col0 < n3);

    float acc[2][4][4];
#pragma unroll
    for (int mi = 0; mi < 2; mi++)
#pragma unroll
        for (int j = 0; j < 4; j++)
#pragma unroll
            for (int r = 0; r < 4; r++) acc[mi][j][r] = 0.f;

#define STAGE(kc, s) do { \
    int k0 = (kc) << 5; \
    _Pragma("unroll") \
    for (int i = 0; i < 2; i++) { \
        int e = tid + i * 256; \
        int r = e >> 2, cs = (e & 3) * 8; \
        size_t ga = (size_t)(row0 + r) * K + k0 + cs; \
        cp16(smem_u32(&sAh[A_OFF(s, r, cs)]), Ah + ga); \
        cp16(smem_u32(&sAl[A_OFF(s, r, cs)]), Al + ga); \
    } \
    { int r = tid >> 2, cs = (tid & 3) * 8; \
      size_t gb = (size_t)(col0 + r) * K + k0 + cs; \
      cp16(smem_u32(&sBh[B_OFF(s, r, cs)]), Bh + gb); \
      cp16(smem_u32(&sBl[B_OFF(s, r, cs)]), Bl + gb); } \
} while (0)

    int nk = K >> 5;
    STAGE(0, 0);
    CP_COMMIT();
    for (int kc = 0; kc < nk; kc++) {
        int cur = kc & 1;
        if (kc + 1 < nk) { STAGE(kc + 1, cur ^ 1); CP_COMMIT(); CP_WAIT1(); }
        else             { CP_WAIT0(); }
        __syncthreads();

#pragma unroll
        for (int ks = 0; ks < 2; ks++) {
            uint32_t aH[2][4], aL[2][4], bH[4][2], bL[4][2];
#pragma unroll
            for (int mi = 0; mi < 2; mi++) {
                int rowa = wm * 32 + mi * 16 + (lane & 15);
                int cola = ks * 16 + (lane >> 4) * 8;
                LDSM_X4(aH[mi], smem_u32(&sAh[A_OFF(cur, rowa, cola)]));
                LDSM_X4(aL[mi], smem_u32(&sAl[A_OFF(cur, rowa, cola)]));
            }
#pragma unroll
            for (int j = 0; j < 4; j++) {
                int l16 = lane & 15;
                int rowb = wn * 32 + j * 8 + (l16 & 7);
                int colb = ks * 16 + ((l16 >> 3) & 1) * 8;
                LDSM_X2(bH[j], smem_u32(&sBh[B_OFF(cur, rowb, colb)]));
                LDSM_X2(bL[j], smem_u32(&sBl[B_OFF(cur, rowb, colb)]));
            }
#pragma unroll
            for (int mi = 0; mi < 2; mi++)
#pragma unroll
                for (int j = 0; j < 4; j++) {
                    MMA16816(acc[mi][j], aH[mi], bH[j]);
                    MMA16816(acc[mi][j], aH[mi], bL[j]);
                }
            if (full3) {
#pragma unroll
                for (int mi = 0; mi < 2; mi++)
#pragma unroll
                    for (int j = 0; j < 4; j++)
                        MMA16816(acc[mi][j], aL[mi], bH[j]);
            }
        }
        __syncthreads();
    }
#undef STAGE

    int g = lane >> 2, t = lane & 3;
#pragma unroll
    for (int mi = 0; mi < 2; mi++)
#pragma unroll
        for (int j = 0; j < 4; j++) {
            int col = col0 + wn * 32 + j * 8 + t * 2;
            float2 bv = *reinterpret_cast<const float2*>(&bias[col]);
            int r0 = row0 + wm * 32 + mi * 16 + g;
            float2 o0 = make_float2(acc[mi][j][0] + bv.x, acc[mi][j][1] + bv.y);
            float2 o1 = make_float2(acc[mi][j][2] + bv.x, acc[mi][j][3] + bv.y);
            *reinterpret_cast<float2*>(&C[(size_t)r0 * N + col]) = o0;
            *reinterpret_cast<float2*>(&C[(size_t)(r0 + 8) * N + col]) = o1;
        }
}

// ------- merged conversions -------
__global__ void __launch_bounds__(256) convert_all_kernel(
    const float* __restrict__ x, const float* __restrict__ qkv_w,
    const float* __restrict__ proj_w)
{
    int bid = blockIdx.x, tid = threadIdx.x;
    if (bid < 2048) {
        int i = (bid * 256 + tid) * 4;
        float4 v = *reinterpret_cast<const float4*>(&x[i]);
        float f[4] = {v.x, v.y, v.z, v.w};
#pragma unroll
        for (int j = 0; j < 4; j++) {
            __half h, l; split1(f[j], h, l);
            g_xhi[i + j] = h; g_xlo[i + j] = l;
        }
    } else if (bid < 2048 + C3) {
        int o = bid - 2048;
        __half h, l; split1(qkv_w[(size_t)tid * C3 + o], h, l);
        g_qwh[(size_t)o * CD + tid] = h;
        g_qwl[(size_t)o * CD + tid] = l;
    } else {
        int o = bid - 2048 - C3;
        __half h, l; split1(proj_w[(size_t)tid * CD + o], h, l);
        g_pwh[(size_t)o * CD + tid] = h;
        g_pwl[(size_t)o * CD + tid] = l;
    }
}

// ---------------- depthwise 3x3, 4 px/thread; q fp32, kv float2 ----------
__global__ void __launch_bounds__(192) dwconv_kernel(
    const float* __restrict__ in, const float* __restrict__ w,
    const float* __restrict__ bias)
{
    int c = threadIdx.x * 4;
    int x0 = blockIdx.x * 4, y = blockIdx.y, b = blockIdx.z;
    float4 bz = *reinterpret_cast<const float4*>(&bias[c]);
    float4 acc[4] = {bz, bz, bz, bz};
#pragma unroll
    for (int ky = 0; ky < 3; ky++) {
        int yy = y + ky - 1;
        if (yy < 0 || yy >= HD) continue;
        const float* rowp = in + ((size_t)(b * HD + yy) * WD) * C3 + c;
        float4 iv[6];
#pragma unroll
        for (int j = 0; j < 6; j++) {
            int xx = x0 - 1 + j;
            iv[j] = (xx >= 0 && xx < WD)
                ? *reinterpret_cast<const float4*>(rowp + (size_t)xx * C3)
                : make_float4(0.f, 0.f, 0.f, 0.f);
        }
#pragma unroll
        for (int kx = 0; kx < 3; kx++) {
            float4 wv = *reinterpret_cast<const float4*>(&w[(ky * 3 + kx) * C3 + c]);
#pragma unroll
            for (int p = 0; p < 4; p++) {
                acc[p].x += wv.x * iv[p + kx].x; acc[p].y += wv.y * iv[p + kx].y;
                acc[p].z += wv.z * iv[p + kx].z; acc[p].w += wv.w * iv[p + kx].w;
            }
        }
    }
#pragma unroll
    for (int p = 0; p < 4; p++) {
        size_t pix = (size_t)(b * HD + y) * WD + x0 + p;
        if (c < CD) {
            *reinterpret_cast<float4*>(&g_q[pix * CD + c]) = acc[p];
        } else if (c < 2 * CD) {          // k -> .x
            float2* bp = &g_kv[pix * CD + (c - CD)];
            bp[0].x = acc[p].x; bp[1].x = acc[p].y;
            bp[2].x = acc[p].z; bp[3].x = acc[p].w;
        } else {                           // v -> .y
            float2* bp = &g_kv[pix * CD + (c - 2 * CD)];
            bp[0].y = acc[p].x; bp[1].y = acc[p].y;
            bp[2].y = acc[p].z; bp[3].y = acc[p].w;
        }
    }
}

// ---------------- fold pconv+proj -> combW^T hi/lo + bias ----------------
__global__ void __launch_bounds__(128) prep_kernel(
    const float* __restrict__ off_pconv_w, const float* __restrict__ off_w,
    const float* __restrict__ off_b, const float* __restrict__ mask_pconv_w,
    const float* __restrict__ mask_w, const float* __restrict__ mask_b)
{
    int o = blockIdx.x;
    int f = blockIdx.y * 128 + threadIdx.x;
    if (o >= 153) {
        g_cwh[(size_t)o * NF + f] = __float2half_rn(0.f);
        g_cwl[(size_t)o * NF + f] = __float2half_rn(0.f);
        if (threadIdx.x == 0 && blockIdx.y == 0) g_combB[o] = 0.f;
        return;
    }
    bool is_mask = (o >= 144);
    int g = 0, j = 0, kk = 0;
    if (!is_mask) { g = o / 18; j = o % 18; } else { kk = o - 144; }

    float s;
    if (f < 576) {
        int t = f >> 6, ic = f & 63;
        s = 0.f;
        if (!is_mask) {
            const float* ow = off_w + (g * 18 + j) * 256;
            const float* pc = off_pconv_w + ((size_t)(g * 64) * 64 + ic) * 9 + t;
#pragma unroll 4
            for (int oc = 0; oc < 64; oc++) s += ow[oc] * pc[(size_t)oc * 64 * 9];
        } else {
            const float* mw = mask_w + kk * 256;
            const float* pc = mask_pconv_w + (size_t)ic * 9 + t;
#pragma unroll 4
            for (int oc = 0; oc < 64; oc++) s += mw[oc] * pc[(size_t)oc * 64 * 9];
        }
    } else {
        int ch = f - 512;
        s = is_mask ? mask_w[kk * 256 + ch] : off_w[(g * 18 + j) * 256 + ch];
    }
    __half h, l; split1(s, h, l);
    g_cwh[(size_t)o * NF + f] = h;
    g_cwl[(size_t)o * NF + f] = l;
    if (threadIdx.x == 0 && blockIdx.y == 0)
        g_combB[o] = is_mask ? mask_b[kk]
                             : (off_b[g * 18 + j] + c_PTS[j] * (float)(2 * g + 1));
}

// ---------------- im2col feature matrix from g_q, hi/lo fp16 -------------
__global__ void __launch_bounds__(256) im2col_kernel()
{
    int bh = blockIdx.x;
    int b = bh >> 6, h = bh & 63;
    int tid = threadIdx.x;
#pragma unroll
    for (int t = 0; t < 9; t++) {
        int yy = h + t / 3 - 1;
        int dx = t % 3 - 1;
        bool rowok = (yy >= 0 && yy < HD);
        const float* rowp = g_q + (size_t)(b * HD + yy) * WD * CD;
#pragma unroll
        for (int it = 0; it < 4; it++) {
            int e = tid + it * 256;
            int px = e >> 4, c4 = (e & 15) << 2;
            int xx = px + dx;
            float4 v = make_float4(0.f, 0.f, 0.f, 0.f);
            if (rowok && xx >= 0 && xx < WD)
                v = *reinterpret_cast<const float4*>(rowp + (size_t)xx * CD + c4);
            size_t oo = (size_t)(bh * 64 + px) * NF + t * 64 + c4;
            __half h0,h1,h2,h3,l0,l1,l2,l3;
            split1(v.x,h0,l0); split1(v.y,h1,l1); split1(v.z,h2,l2); split1(v.w,h3,l3);
            *reinterpret_cast<__half2*>(&g_fh[oo])   = __halves2half2(h0,h1);
            *reinterpret_cast<__half2*>(&g_fh[oo+2]) = __halves2half2(h2,h3);
            *reinterpret_cast<__half2*>(&g_fl[oo])   = __halves2half2(l0,l1);
            *reinterpret_cast<__half2*>(&g_fl[oo+2]) = __halves2half2(l2,l3);
        }
    }
    const float* crow = g_q + (size_t)(b * HD + h) * WD * CD;
#pragma unroll
    for (int it = 0; it < 12; it++) {
        int e = tid + it * 256;
        int px = e / 48, c4 = (e % 48) << 2;
        float4 v = *reinterpret_cast<const float4*>(crow + (size_t)px * CD + 64 + c4);
        size_t oo = (size_t)(bh * 64 + px) * NF + 576 + c4;
        __half h0,h1,h2,h3,l0,l1,l2,l3;
        split1(v.x,h0,l0); split1(v.y,h1,l1); split1(v.z,h2,l2); split1(v.w,h3,l3);
        *reinterpret_cast<__half2*>(&g_fh[oo])   = __halves2half2(h0,h1);
        *reinterpret_cast<__half2*>(&g_fh[oo+2]) = __halves2half2(h2,h3);
        *reinterpret_cast<__half2*>(&g_fl[oo])   = __halves2half2(l0,l1);
        *reinterpret_cast<__half2*>(&g_fl[oo+2]) = __halves2half2(l2,l3);
    }
}

// ---------------- deformable attention: warp per (b,g,pixel) --------------
__global__ void __launch_bounds__(256) attn_kernel()
{
    int warp = threadIdx.x >> 5, lane = threadIdx.x & 31;
    int px = blockIdx.x * 8 + warp;
    int g = blockIdx.y, b = blockIdx.z;
    int h = px >> 6, w = px & 63;

    const float* om = g_offmask + ((size_t)(b * HD + h) * WD + w) * NOP;
    float qv = g_q[((size_t)(b * HD + h) * WD + w) * CD + g * HCD + lane]
             * 0.17677669529663687f;

    float attn[KP], vk[KP];
#pragma unroll
    for (int k = 0; k < KP; k++) {
        float ox = om[g * 18 + 2 * k], oy = om[g * 18 + 2 * k + 1], mk = om[144 + k];
        float cx = fminf(fmaxf((float)w + ox, 0.f), (float)(WD - 1));
        float cy = fminf(fmaxf((float)h + oy, 0.f), (float)(HD - 1));
        float x0f = floorf(cx), y0f = floorf(cy);
        float fx = cx - x0f, fy = cy - y0f;
        int x0 = (int)x0f, y0 = (int)y0f;
        int x1 = min(x0 + 1, WD - 1), y1 = min(y0 + 1, HD - 1);
        size_t i00 = ((size_t)(b * HD + y0) * WD + x0) * CD + g * HCD + lane;
        size_t i01 = ((size_t)(b * HD + y0) * WD + x1) * CD + g * HCD + lane;
        size_t i10 = ((size_t)(b * HD + y1) * WD + x0) * CD + g * HCD + lane;
        size_t i11 = ((size_t)(b * HD + y1) * WD + x1) * CD + g * HCD + lane;
        float2 kv00 = g_kv[i00], kv01 = g_kv[i01];
        float2 kv10 = g_kv[i10], kv11 = g_kv[i11];
        float w00 = (1.f - fx) * (1.f - fy), w01 = fx * (1.f - fy);
        float w10 = (1.f - fx) * fy,         w11 = fx * fy;
        float kvv = kv00.x*w00 + kv01.x*w01 + kv10.x*w10 + kv11.x*w11;
        float vvv = kv00.y*w00 + kv01.y*w01 + kv10.y*w10 + kv11.y*w11;
        kvv *= mk; vvv *= mk;
        float d = qv * kvv;
#pragma unroll
        for (int s = 16; s; s >>= 1) d += __shfl_xor_sync(0xffffffffu, d, s);
        attn[k] = d;
        vk[k] = vvv;
    }
    float m = attn[0];
#pragma unroll
    for (int k = 1; k < KP; k++) m = fmaxf(m, attn[k]);
    float ssum = 0.f, o = 0.f;
#pragma unroll
    for (int k = 0; k < KP; k++) {
        float e = __expf(attn[k] - m);
        ssum += e;
        o += e * vk[k];
    }
    o /= ssum;
    size_t oi = ((size_t)((b * HD + h) * WD + w)) * CD + g * HCD + lane;
    __half hh, ll; split1(o, hh, ll);
    g_aoh[oi] = hh; g_aol[oi] = ll;
}

// --------------------------------- launch ---------------------------------
extern "C" void kernel_launch(void* const* d_in, const int* in_sizes, int n_in,
                              void* d_out, int out_size)
{
    const float* x            = (const float*)d_in[0];
    const float* qkv_w        = (const float*)d_in[1];
    const float* qkv_b        = (const float*)d_in[2];
    const float* dw_w         = (const float*)d_in[3];
    const float* dw_b         = (const float*)d_in[4];
    const float* off_pconv_w  = (const float*)d_in[5];
    const float* off_w        = (const float*)d_in[6];
    const float* off_b        = (const float*)d_in[7];
    const float* mask_pconv_w = (const float*)d_in[8];
    const float* mask_w       = (const float*)d_in[9];
    const float* mask_b       = (const float*)d_in[10];
    const float* proj_w       = (const float*)d_in[11];
    const float* proj_b       = (const float*)d_in[12];
    float* out = (float*)d_out;

    cudaFuncSetAttribute(gemm_kernel,
                         cudaFuncAttributeMaxDynamicSharedMemorySize, GEMM_SMEM);

    __half *xh, *xl, *qwh, *qwl, *pwh, *pwl, *cwh, *cwl, *fh, *fl, *aoh, *aol;
    float *qkv, *combB, *offmask;
    cudaGetSymbolAddress((void**)&xh, g_xhi);   cudaGetSymbolAddress((void**)&xl, g_xlo);
    cudaGetSymbolAddress((void**)&qwh, g_qwh);  cudaGetSymbolAddress((void**)&qwl, g_qwl);
    cudaGetSymbolAddress((void**)&pwh, g_pwh);  cudaGetSymbolAddress((void**)&pwl, g_pwl);
    cudaGetSymbolAddress((void**)&cwh, g_cwh);  cudaGetSymbolAddress((void**)&cwl, g_cwl);
    cudaGetSymbolAddress((void**)&fh, g_fh);    cudaGetSymbolAddress((void**)&fl, g_fl);
    cudaGetSymbolAddress((void**)&aoh, g_aoh);  cudaGetSymbolAddress((void**)&aol, g_aol);
    cudaGetSymbolAddress((void**)&qkv, g_qkv);
    cudaGetSymbolAddress((void**)&combB, g_combB);
    cudaGetSymbolAddress((void**)&offmask, g_offmask);

    convert_all_kernel<<<2048 + C3 + CD, 256>>>(x, qkv_w, proj_w);
    {
        dim3 grid(NOP, NF / 128);
        prep_kernel<<<grid, 128>>>(off_pconv_w, off_w, off_b,
                                   mask_pconv_w, mask_w, mask_b);
    }
    // qkv GEMM: q columns (<256) full split, k/v columns 2-product
    {
        dim3 grid(C3 / 64, MR / 128);
        gemm_kernel<<<grid, 256, GEMM_SMEM>>>(xh, xl, qwh, qwl, qkv_b, qkv,
                                              C3, CD, CD);
    }
    {
        dim3 grid(WD / 4, HD, BD);
        dwconv_kernel<<<grid, 192>>>(qkv, dw_w, dw_b);
    }
    im2col_kernel<<<BD * HD, 256>>>();
    // offset/mask GEMM: full split everywhere (offsets are sensitive)
    {
        dim3 grid(NOP / 64, MR / 128);
        gemm_kernel<<<grid, 256, GEMM_SMEM>>>(fh, fl, cwh, cwl, combB, offmask,
                                              NOP, NF, NOP);
    }
    {
        dim3 grid(PD / 8, GD, BD);
        attn_kernel<<<grid, 256>>>();
    }
    // proj GEMM: 2-product everywhere
    {
        dim3 grid(CD / 64, MR / 128);
        gemm_kernel<<<grid, 256, GEMM_SMEM>>>(aoh, aol, pwh, pwl, proj_b, out,
                                              CD, CD, 0);
    }
}

// round 10
// speedup vs baseline: 1.0291x; 1.0190x over previous
#include <cuda_runtime.h>
#include <cuda_fp16.h>
#include <cstdint>

#define BD 2
#define HD 64
#define WD 64
#define CD 256
#define GD 8
#define KP 9
#define HCD 32
#define PD (HD*WD)
#define C3 (3*CD)        // 768
#define NOP 192          // padded offset/mask outputs (153 real)
#define NF 768
#define MR (BD*PD)       // 8192

// ---------------- scratch (device globals; no allocation) ----------------
__device__ float  g_qkv[MR*C3];          // after qkv GEMM
__device__ __half g_qh[MR*CD], g_ql[MR*CD]; // q after dwconv, split hi/lo
__device__ float2 g_kv[MR*CD];           // {k,v} fp32 interleaved after dwconv
__device__ float  g_offmask[MR*NOP];
__device__ float  g_combB[NOP];
__device__ __half g_xhi[MR*CD], g_xlo[MR*CD];
__device__ __half g_qwh[C3*CD], g_qwl[C3*CD];      // qkv_w^T hi/lo
__device__ __half g_pwh[CD*CD], g_pwl[CD*CD];      // proj_w^T hi/lo
__device__ __half g_cwh[NOP*NF], g_cwl[NOP*NF];    // combW^T hi/lo
__device__ __half g_aoh[MR*CD], g_aol[MR*CD];      // attention out

__constant__ float c_PTS[18] = {-1,-1,-1,0,-1,1,0,-1,0,0,0,1,1,-1,1,0,1,1};

// ---------------- helpers ----------------
__device__ __forceinline__ uint32_t smem_u32(const void* p) {
    uint32_t a;
    asm("{ .reg .u64 t; cvta.to.shared.u64 t, %1; cvt.u32.u64 %0, t; }" : "=r"(a) : "l"(p));
    return a;
}
__device__ __forceinline__ void cp16(uint32_t dst, const void* src) {
    asm volatile("cp.async.cg.shared.global [%0], [%1], 16;" :: "r"(dst), "l"(src));
}
#define CP_COMMIT() asm volatile("cp.async.commit_group;" ::: "memory")
#define CP_WAIT0()  asm volatile("cp.async.wait_group 0;" ::: "memory")
#define CP_WAIT1()  asm volatile("cp.async.wait_group 1;" ::: "memory")
#define LDSM_X4(r, a) asm volatile( \
    "ldmatrix.sync.aligned.m8n8.x4.shared.b16 {%0,%1,%2,%3}, [%4];" \
    : "=r"((r)[0]),"=r"((r)[1]),"=r"((r)[2]),"=r"((r)[3]) : "r"(a))
#define LDSM_X2(r, a) asm volatile( \
    "ldmatrix.sync.aligned.m8n8.x2.shared.b16 {%0,%1}, [%2];" \
    : "=r"((r)[0]),"=r"((r)[1]) : "r"(a))
#define MMA16816(c, a, b) asm volatile( \
    "mma.sync.aligned.m16n8k16.row.col.f32.f16.f16.f32 " \
    "{%0,%1,%2,%3}, {%4,%5,%6,%7}, {%8,%9}, {%0,%1,%2,%3};" \
    : "+f"((c)[0]),"+f"((c)[1]),"+f"((c)[2]),"+f"((c)[3]) \
    : "r"((a)[0]),"r"((a)[1]),"r"((a)[2]),"r"((a)[3]), "r"((b)[0]),"r"((b)[1]))

__device__ __forceinline__ void split1(float v, __half& hi, __half& lo) {
    hi = __float2half_rn(v);
    lo = __float2half_rn(v - __half2float(hi));
}

// ============ split-fp16 tensor-core GEMM, double-buffered ============
// C[M,N] = A·B^T + bias. Columns < n3 -> 3 products, else 2 (drop AlBh).
#define A_OFF(s,r,c) ((s)*128*40 + (r)*40 + (c))
#define B_OFF(s,r,c) ((s)*64*40 + (r)*40 + (c))
#define GEMM_SMEM (2*(2*128*40 + 2*64*40) * 2)   // 61440 bytes

__global__ void __launch_bounds__(256, 2) gemm_kernel(
    const __half* __restrict__ Ah, const __half* __restrict__ Al,
    const __half* __restrict__ Bh, const __half* __restrict__ Bl,
    const float* __restrict__ bias, float* __restrict__ C, int N, int K, int n3)
{
    extern __shared__ __half sm[];
    __half* sAh = sm;
    __half* sAl = sAh + 2*128*40;
    __half* sBh = sAl + 2*128*40;
    __half* sBl = sBh + 2*64*40;

    int tid = threadIdx.x;
    int warp = tid >> 5, lane = tid & 31;
    int wm = warp >> 1, wn = warp & 1;
    int row0 = blockIdx.y * 128, col0 = blockIdx.x * 64;
    bool full3 = (col0 < n3);

    float acc[2][4][4];
#pragma unroll
    for (int mi = 0; mi < 2; mi++)
#pragma unroll
        for (int j = 0; j < 4; j++)
#pragma unroll
            for (int r = 0; r < 4; r++) acc[mi][j][r] = 0.f;

#define STAGE(kc, s) do { \
    int k0 = (kc) << 5; \
    _Pragma("unroll") \
    for (int i = 0; i < 2; i++) { \
        int e = tid + i * 256; \
        int r = e >> 2, cs = (e & 3) * 8; \
        size_t ga = (size_t)(row0 + r) * K + k0 + cs; \
        cp16(smem_u32(&sAh[A_OFF(s, r, cs)]), Ah + ga); \
        cp16(smem_u32(&sAl[A_OFF(s, r, cs)]), Al + ga); \
    } \
    { int r = tid >> 2, cs = (tid & 3) * 8; \
      size_t gb = (size_t)(col0 + r) * K + k0 + cs; \
      cp16(smem_u32(&sBh[B_OFF(s, r, cs)]), Bh + gb); \
      cp16(smem_u32(&sBl[B_OFF(s, r, cs)]), Bl + gb); } \
} while (0)

    int nk = K >> 5;
    STAGE(0, 0);
    CP_COMMIT();
    for (int kc = 0; kc < nk; kc++) {
        int cur = kc & 1;
        if (kc + 1 < nk) { STAGE(kc + 1, cur ^ 1); CP_COMMIT(); CP_WAIT1(); }
        else             { CP_WAIT0(); }
        __syncthreads();

#pragma unroll
        for (int ks = 0; ks < 2; ks++) {
            uint32_t aH[2][4], aL[2][4], bH[4][2], bL[4][2];
#pragma unroll
            for (int mi = 0; mi < 2; mi++) {
                int rowa = wm * 32 + mi * 16 + (lane & 15);
                int cola = ks * 16 + (lane >> 4) * 8;
                LDSM_X4(aH[mi], smem_u32(&sAh[A_OFF(cur, rowa, cola)]));
                LDSM_X4(aL[mi], smem_u32(&sAl[A_OFF(cur, rowa, cola)]));
            }
#pragma unroll
            for (int j = 0; j < 4; j++) {
                int l16 = lane & 15;
                int rowb = wn * 32 + j * 8 + (l16 & 7);
                int colb = ks * 16 + ((l16 >> 3) & 1) * 8;
                LDSM_X2(bH[j], smem_u32(&sBh[B_OFF(cur, rowb, colb)]));
                LDSM_X2(bL[j], smem_u32(&sBl[B_OFF(cur, rowb, colb)]));
            }
#pragma unroll
            for (int mi = 0; mi < 2; mi++)
#pragma unroll
                for (int j = 0; j < 4; j++) {
                    MMA16816(acc[mi][j], aH[mi], bH[j]);
                    MMA16816(acc[mi][j], aH[mi], bL[j]);
                }
            if (full3) {
#pragma unroll
                for (int mi = 0; mi < 2; mi++)
#pragma unroll
                    for (int j = 0; j < 4; j++)
                        MMA16816(acc[mi][j], aL[mi], bH[j]);
            }
        }
        __syncthreads();
    }
#undef STAGE

    int g = lane >> 2, t = lane & 3;
#pragma unroll
    for (int mi = 0; mi < 2; mi++)
#pragma unroll
        for (int j = 0; j < 4; j++) {
            int col = col0 + wn * 32 + j * 8 + t * 2;
            float2 bv = *reinterpret_cast<const float2*>(&bias[col]);
            int r0 = row0 + wm * 32 + mi * 16 + g;
            float2 o0 = make_float2(acc[mi][j][0] + bv.x, acc[mi][j][1] + bv.y);
            float2 o1 = make_float2(acc[mi][j][2] + bv.x, acc[mi][j][3] + bv.y);
            *reinterpret_cast<float2*>(&C[(size_t)r0 * N + col]) = o0;
            *reinterpret_cast<float2*>(&C[(size_t)(r0 + 8) * N + col]) = o1;
        }
}

// ============ fused offset/mask GEMM: im2col gather + split-fp16 MMA ========
// C[8192,192] = feat(q) · combW^T + combB. A gathered on the fly from g_qh/g_ql.
// Single-buffered; 128x64 tile, BK=32, 3 products (offsets are sensitive).
__global__ void __launch_bounds__(256, 2) offmask_gemm_kernel()
{
    __shared__ __half sAh[128*40], sAl[128*40], sBh[64*40], sBl[64*40];
    int tid = threadIdx.x;
    int warp = tid >> 5, lane = tid & 31;
    int wm = warp >> 1, wn = warp & 1;
    int row0 = blockIdx.y * 128, col0 = blockIdx.x * 64;
    int b = row0 >> 12;                 // /4096
    int hbase = (row0 & 4095) >> 6;     // image row of pixel 0 (block = 2 rows)

    float acc[2][4][4];
#pragma unroll
    for (int mi = 0; mi < 2; mi++)
#pragma unroll
        for (int j = 0; j < 4; j++)
#pragma unroll
            for (int r = 0; r < 4; r++) acc[mi][j][r] = 0.f;

    for (int kc = 0; kc < NF / 32; kc++) {
        int f0 = kc << 5;
        int dy, dx, cofs;
        if (f0 < 576) { int t = f0 >> 6; dy = t / 3 - 1; dx = t % 3 - 1; cofs = f0 & 63; }
        else          { dy = 0; dx = 0; cofs = 64 + (f0 - 576); }

        __syncthreads();   // previous compute done; smem reusable
        // A gather: 128 px x 32 features (hi & lo), 8B per slot
#pragma unroll
        for (int i = 0; i < 4; i++) {
            int idx = tid + i * 256;        // 0..1023
            int px = idx >> 3;
            int c4 = (idx & 7) << 2;        // feature quad within chunk
            int hh = hbase + (px >> 6) + dy;
            int xx = (px & 63) + dx;
            uint2 hv = make_uint2(0u, 0u), lv = make_uint2(0u, 0u);
            if (hh >= 0 && hh < HD && xx >= 0 && xx < WD) {
                size_t base = ((size_t)(b * HD + hh) * WD + xx) * CD + cofs + c4;
                hv = *reinterpret_cast<const uint2*>(&g_qh[base]);
                lv = *reinterpret_cast<const uint2*>(&g_ql[base]);
            }
            *reinterpret_cast<uint2*>(&sAh[px * 40 + c4]) = hv;
            *reinterpret_cast<uint2*>(&sAl[px * 40 + c4]) = lv;
        }
        // B stage via cp.async
        {
            int r = tid >> 2, cs = (tid & 3) * 8;
            size_t gb = (size_t)(col0 + r) * NF + f0 + cs;
            cp16(smem_u32(&sBh[r * 40 + cs]), g_cwh + gb);
            cp16(smem_u32(&sBl[r * 40 + cs]), g_cwl + gb);
        }
        CP_COMMIT();
        CP_WAIT0();
        __syncthreads();

#pragma unroll
        for (int ks = 0; ks < 2; ks++) {
            uint32_t aH[2][4], aL[2][4], bH[4][2], bL[4][2];
#pragma unroll
            for (int mi = 0; mi < 2; mi++) {
                int rowa = wm * 32 + mi * 16 + (lane & 15);
                int cola = ks * 16 + (lane >> 4) * 8;
                LDSM_X4(aH[mi], smem_u32(&sAh[rowa * 40 + cola]));
                LDSM_X4(aL[mi], smem_u32(&sAl[rowa * 40 + cola]));
            }
#pragma unroll
            for (int j = 0; j < 4; j++) {
                int l16 = lane & 15;
                int rowb = wn * 32 + j * 8 + (l16 & 7);
                int colb = ks * 16 + ((l16 >> 3) & 1) * 8;
                LDSM_X2(bH[j], smem_u32(&sBh[rowb * 40 + colb]));
                LDSM_X2(bL[j], smem_u32(&sBl[rowb * 40 + colb]));
            }
#pragma unroll
            for (int mi = 0; mi < 2; mi++)
#pragma unroll
                for (int j = 0; j < 4; j++) {
                    MMA16816(acc[mi][j], aH[mi], bH[j]);
                    MMA16816(acc[mi][j], aH[mi], bL[j]);
                    MMA16816(acc[mi][j], aL[mi], bH[j]);
                }
        }
    }

    int g = lane >> 2, t = lane & 3;
#pragma unroll
    for (int mi = 0; mi < 2; mi++)
#pragma unroll
        for (int j = 0; j < 4; j++) {
            int col = col0 + wn * 32 + j * 8 + t * 2;
            float2 bv = *reinterpret_cast<const float2*>(&g_combB[col]);
            int r0 = row0 + wm * 32 + mi * 16 + g;
            float2 o0 = make_float2(acc[mi][j][0] + bv.x, acc[mi][j][1] + bv.y);
            float2 o1 = make_float2(acc[mi][j][2] + bv.x, acc[mi][j][3] + bv.y);
            *reinterpret_cast<float2*>(&g_offmask[(size_t)r0 * NOP + col]) = o0;
            *reinterpret_cast<float2*>(&g_offmask[(size_t)(r0 + 8) * NOP + col]) = o1;
        }
}

// ------- merged conversions -------
__global__ void __launch_bounds__(256) convert_all_kernel(
    const float* __restrict__ x, const float* __restrict__ qkv_w,
    const float* __restrict__ proj_w)
{
    int bid = blockIdx.x, tid = threadIdx.x;
    if (bid < 2048) {
        int i = (bid * 256 + tid) * 4;
        float4 v = *reinterpret_cast<const float4*>(&x[i]);
        float f[4] = {v.x, v.y, v.z, v.w};
#pragma unroll
        for (int j = 0; j < 4; j++) {
            __half h, l; split1(f[j], h, l);
            g_xhi[i + j] = h; g_xlo[i + j] = l;
        }
    } else if (bid < 2048 + C3) {
        int o = bid - 2048;
        __half h, l; split1(qkv_w[(size_t)tid * C3 + o], h, l);
        g_qwh[(size_t)o * CD + tid] = h;
        g_qwl[(size_t)o * CD + tid] = l;
    } else {
        int o = bid - 2048 - C3;
        __half h, l; split1(proj_w[(size_t)tid * CD + o], h, l);
        g_pwh[(size_t)o * CD + tid] = h;
        g_pwl[(size_t)o * CD + tid] = l;
    }
}

// ---------------- depthwise 3x3, 4 px/thread; q hi/lo fp16, kv float2 -----
__global__ void __launch_bounds__(192) dwconv_kernel(
    const float* __restrict__ in, const float* __restrict__ w,
    const float* __restrict__ bias)
{
    int c = threadIdx.x * 4;
    int x0 = blockIdx.x * 4, y = blockIdx.y, b = blockIdx.z;
    float4 bz = *reinterpret_cast<const float4*>(&bias[c]);
    float4 acc[4] = {bz, bz, bz, bz};
#pragma unroll
    for (int ky = 0; ky < 3; ky++) {
        int yy = y + ky - 1;
        if (yy < 0 || yy >= HD) continue;
        const float* rowp = in + ((size_t)(b * HD + yy) * WD) * C3 + c;
        float4 iv[6];
#pragma unroll
        for (int j = 0; j < 6; j++) {
            int xx = x0 - 1 + j;
            iv[j] = (xx >= 0 && xx < WD)
                ? *reinterpret_cast<const float4*>(rowp + (size_t)xx * C3)
                : make_float4(0.f, 0.f, 0.f, 0.f);
        }
#pragma unroll
        for (int kx = 0; kx < 3; kx++) {
            float4 wv = *reinterpret_cast<const float4*>(&w[(ky * 3 + kx) * C3 + c]);
#pragma unroll
            for (int p = 0; p < 4; p++) {
                acc[p].x += wv.x * iv[p + kx].x; acc[p].y += wv.y * iv[p + kx].y;
                acc[p].z += wv.z * iv[p + kx].z; acc[p].w += wv.w * iv[p + kx].w;
            }
        }
    }
#pragma unroll
    for (int p = 0; p < 4; p++) {
        size_t pix = (size_t)(b * HD + y) * WD + x0 + p;
        if (c < CD) {                      // q -> split hi/lo fp16
            __half h0,h1,h2,h3,l0,l1,l2,l3;
            split1(acc[p].x,h0,l0); split1(acc[p].y,h1,l1);
            split1(acc[p].z,h2,l2); split1(acc[p].w,h3,l3);
            size_t o = pix * CD + c;
            *reinterpret_cast<__half2*>(&g_qh[o])   = __halves2half2(h0,h1);
            *reinterpret_cast<__half2*>(&g_qh[o+2]) = __halves2half2(h2,h3);
            *reinterpret_cast<__half2*>(&g_ql[o])   = __halves2half2(l0,l1);
            *reinterpret_cast<__half2*>(&g_ql[o+2]) = __halves2half2(l2,l3);
        } else if (c < 2 * CD) {           // k -> .x
            float2* bp = &g_kv[pix * CD + (c - CD)];
            bp[0].x = acc[p].x; bp[1].x = acc[p].y;
            bp[2].x = acc[p].z; bp[3].x = acc[p].w;
        } else {                           // v -> .y
            float2* bp = &g_kv[pix * CD + (c - 2 * CD)];
            bp[0].y = acc[p].x; bp[1].y = acc[p].y;
            bp[2].y = acc[p].z; bp[3].y = acc[p].w;
        }
    }
}

// ---------------- fold pconv+proj -> combW^T hi/lo + bias ----------------
__global__ void __launch_bounds__(128) prep_kernel(
    const float* __restrict__ off_pconv_w, const float* __restrict__ off_w,
    const float* __restrict__ off_b, const float* __restrict__ mask_pconv_w,
    const float* __restrict__ mask_w, const float* __restrict__ mask_b)
{
    int o = blockIdx.x;
    int f = blockIdx.y * 128 + threadIdx.x;
    if (o >= 153) {
        g_cwh[(size_t)o * NF + f] = __float2half_rn(0.f);
        g_cwl[(size_t)o * NF + f] = __float2half_rn(0.f);
        if (threadIdx.x == 0 && blockIdx.y == 0) g_combB[o] = 0.f;
        return;
    }
    bool is_mask = (o >= 144);
    int g = 0, j = 0, kk = 0;
    if (!is_mask) { g = o / 18; j = o % 18; } else { kk = o - 144; }

    float s;
    if (f < 576) {
        int t = f >> 6, ic = f & 63;
        s = 0.f;
        if (!is_mask) {
            const float* ow = off_w + (g * 18 + j) * 256;
            const float* pc = off_pconv_w + ((size_t)(g * 64) * 64 + ic) * 9 + t;
#pragma unroll 4
            for (int oc = 0; oc < 64; oc++) s += ow[oc] * pc[(size_t)oc * 64 * 9];
        } else {
            const float* mw = mask_w + kk * 256;
            const float* pc = mask_pconv_w + (size_t)ic * 9 + t;
#pragma unroll 4
            for (int oc = 0; oc < 64; oc++) s += mw[oc] * pc[(size_t)oc * 64 * 9];
        }
    } else {
        int ch = f - 512;
        s = is_mask ? mask_w[kk * 256 + ch] : off_w[(g * 18 + j) * 256 + ch];
    }
    __half h, l; split1(s, h, l);
    g_cwh[(size_t)o * NF + f] = h;
    g_cwl[(size_t)o * NF + f] = l;
    if (threadIdx.x == 0 && blockIdx.y == 0)
        g_combB[o] = is_mask ? mask_b[kk]
                             : (off_b[g * 18 + j] + c_PTS[j] * (float)(2 * g + 1));
}

// ---------------- deformable attention: warp per (b,g,pixel) --------------
__global__ void __launch_bounds__(256) attn_kernel()
{
    int warp = threadIdx.x >> 5, lane = threadIdx.x & 31;
    int px = blockIdx.x * 8 + warp;
    int g = blockIdx.y, b = blockIdx.z;
    int h = px >> 6, w = px & 63;

    const float* om = g_offmask + ((size_t)(b * HD + h) * WD + w) * NOP;
    size_t qi = ((size_t)(b * HD + h) * WD + w) * CD + g * HCD + lane;
    float qv = (__half2float(g_qh[qi]) + __half2float(g_ql[qi]))
             * 0.17677669529663687f;

    float attn[KP], vk[KP];
#pragma unroll
    for (int k = 0; k < KP; k++) {
        float ox = om[g * 18 + 2 * k], oy = om[g * 18 + 2 * k + 1], mk = om[144 + k];
        float cx = fminf(fmaxf((float)w + ox, 0.f), (float)(WD - 1));
        float cy = fminf(fmaxf((float)h + oy, 0.f), (float)(HD - 1));
        float x0f = floorf(cx), y0f = floorf(cy);
        float fx = cx - x0f, fy = cy - y0f;
        int x0 = (int)x0f, y0 = (int)y0f;
        int x1 = min(x0 + 1, WD - 1), y1 = min(y0 + 1, HD - 1);
        size_t i00 = ((size_t)(b * HD + y0) * WD + x0) * CD + g * HCD + lane;
        size_t i01 = ((size_t)(b * HD + y0) * WD + x1) * CD + g * HCD + lane;
        size_t i10 = ((size_t)(b * HD + y1) * WD + x0) * CD + g * HCD + lane;
        size_t i11 = ((size_t)(b * HD + y1) * WD + x1) * CD + g * HCD + lane;
        float2 kv00 = g_kv[i00], kv01 = g_kv[i01];
        float2 kv10 = g_kv[i10], kv11 = g_kv[i11];
        float w00 = (1.f - fx) * (1.f - fy), w01 = fx * (1.f - fy);
        float w10 = (1.f - fx) * fy,         w11 = fx * fy;
        float kvv = kv00.x*w00 + kv01.x*w01 + kv10.x*w10 + kv11.x*w11;
        float vvv = kv00.y*w00 + kv01.y*w01 + kv10.y*w10 + kv11.y*w11;
        kvv *= mk; vvv *= mk;
        float d = qv * kvv;
#pragma unroll
        for (int s = 16; s; s >>= 1) d += __shfl_xor_sync(0xffffffffu, d, s);
        attn[k] = d;
        vk[k] = vvv;
    }
    float m = attn[0];
#pragma unroll
    for (int k = 1; k < KP; k++) m = fmaxf(m, attn[k]);
    float ssum = 0.f, o = 0.f;
#pragma unroll
    for (int k = 0; k < KP; k++) {
        float e = __expf(attn[k] - m);
        ssum += e;
        o += e * vk[k];
    }
    o /= ssum;
    size_t oi = ((size_t)((b * HD + h) * WD + w)) * CD + g * HCD + lane;
    __half hh, ll; split1(o, hh, ll);
    g_aoh[oi] = hh; g_aol[oi] = ll;
}

// --------------------------------- launch ---------------------------------
extern "C" void kernel_launch(void* const* d_in, const int* in_sizes, int n_in,
                              void* d_out, int out_size)
{
    const float* x            = (const float*)d_in[0];
    const float* qkv_w        = (const float*)d_in[1];
    const float* qkv_b        = (const float*)d_in[2];
    const float* dw_w         = (const float*)d_in[3];
    const float* dw_b         = (const float*)d_in[4];
    const float* off_pconv_w  = (const float*)d_in[5];
    const float* off_w        = (const float*)d_in[6];
    const float* off_b        = (const float*)d_in[7];
    const float* mask_pconv_w = (const float*)d_in[8];
    const float* mask_w       = (const float*)d_in[9];
    const float* mask_b       = (const float*)d_in[10];
    const float* proj_w       = (const float*)d_in[11];
    const float* proj_b       = (const float*)d_in[12];
    float* out = (float*)d_out;

    cudaFuncSetAttribute(gemm_kernel,
                         cudaFuncAttributeMaxDynamicSharedMemorySize, GEMM_SMEM);

    __half *xh, *xl, *qwh, *qwl, *pwh, *pwl, *aoh, *aol;
    float *qkv;
    cudaGetSymbolAddress((void**)&xh, g_xhi);   cudaGetSymbolAddress((void**)&xl, g_xlo);
    cudaGetSymbolAddress((void**)&qwh, g_qwh);  cudaGetSymbolAddress((void**)&qwl, g_qwl);
    cudaGetSymbolAddress((void**)&pwh, g_pwh);  cudaGetSymbolAddress((void**)&pwl, g_pwl);
    cudaGetSymbolAddress((void**)&aoh, g_aoh);  cudaGetSymbolAddress((void**)&aol, g_aol);
    cudaGetSymbolAddress((void**)&qkv, g_qkv);

    convert_all_kernel<<<2048 + C3 + CD, 256>>>(x, qkv_w, proj_w);
    {
        dim3 grid(NOP, NF / 128);
        prep_kernel<<<grid, 128>>>(off_pconv_w, off_w, off_b,
                                   mask_pconv_w, mask_w, mask_b);
    }
    // qkv GEMM: q columns (<256) full split, k/v columns 2-product
    {
        dim3 grid(C3 / 64, MR / 128);
        gemm_kernel<<<grid, 256, GEMM_SMEM>>>(xh, xl, qwh, qwl, qkv_b, qkv,
                                              C3, CD, CD);
    }
    {
        dim3 grid(WD / 4, HD, BD);
        dwconv_kernel<<<grid, 192>>>(qkv, dw_w, dw_b);
    }
    // fused im2col + offset/mask GEMM
    {
        dim3 grid(NOP / 64, MR / 128);
        offmask_gemm_kernel<<<grid, 256>>>();
    }
    {
        dim3 grid(PD / 8, GD, BD);
        attn_kernel<<<grid, 256>>>();
    }
    // proj GEMM: 2-product everywhere
    {
        dim3 grid(CD / 64, MR / 128);
        gemm_kernel<<<grid, 256, GEMM_SMEM>>>(aoh, aol, pwh, pwl, proj_b, out,
                                              CD, CD, 0);
    }
}

// round 11
// speedup vs baseline: 1.0761x; 1.0457x over previous
#include <cuda_runtime.h>
#include <cuda_fp16.h>
#include <cstdint>

#define BD 2
#define HD 64
#define WD 64
#define CD 256
#define GD 8
#define KP 9
#define HCD 32
#define PD (HD*WD)
#define C3 (3*CD)        // 768
#define NOP 192          // padded offset/mask outputs (153 real)
#define NF 768
#define MR (BD*PD)       // 8192

// ---------------- scratch (device globals; no allocation) ----------------
__device__ float  g_qkv[MR*C3];
__device__ __half g_qh[MR*CD], g_ql[MR*CD];
__device__ float2 g_kv[MR*CD];
__device__ float  g_offmask[MR*NOP];
__device__ float  g_combB[NOP];
__device__ __half g_xhi[MR*CD], g_xlo[MR*CD];
__device__ __half g_qwh[C3*CD], g_qwl[C3*CD];
__device__ __half g_pwh[CD*CD], g_pwl[CD*CD];
__device__ __half g_cwh[NOP*NF], g_cwl[NOP*NF];
__device__ __half g_aoh[MR*CD], g_aol[MR*CD];

__constant__ float c_PTS[18] = {-1,-1,-1,0,-1,1,0,-1,0,0,0,1,1,-1,1,0,1,1};

// ---------------- helpers ----------------
__device__ __forceinline__ uint32_t smem_u32(const void* p) {
    uint32_t a;
    asm("{ .reg .u64 t; cvta.to.shared.u64 t, %1; cvt.u32.u64 %0, t; }" : "=r"(a) : "l"(p));
    return a;
}
__device__ __forceinline__ void cp16(uint32_t dst, const void* src) {
    asm volatile("cp.async.cg.shared.global [%0], [%1], 16;" :: "r"(dst), "l"(src));
}
#define CP_COMMIT() asm volatile("cp.async.commit_group;" ::: "memory")
#define CP_WAIT0()  asm volatile("cp.async.wait_group 0;" ::: "memory")
#define CP_WAIT1()  asm volatile("cp.async.wait_group 1;" ::: "memory")
#define LDSM_X4(r, a) asm volatile( \
    "ldmatrix.sync.aligned.m8n8.x4.shared.b16 {%0,%1,%2,%3}, [%4];" \
    : "=r"((r)[0]),"=r"((r)[1]),"=r"((r)[2]),"=r"((r)[3]) : "r"(a))
#define MMA16816(c, a, b) asm volatile( \
    "mma.sync.aligned.m16n8k16.row.col.f32.f16.f16.f32 " \
    "{%0,%1,%2,%3}, {%4,%5,%6,%7}, {%8,%9}, {%0,%1,%2,%3};" \
    : "+f"((c)[0]),"+f"((c)[1]),"+f"((c)[2]),"+f"((c)[3]) \
    : "r"((a)[0]),"r"((a)[1]),"r"((a)[2]),"r"((a)[3]), "r"((b)[0]),"r"((b)[1]))

__device__ __forceinline__ void split1(float v, __half& hi, __half& lo) {
    hi = __float2half_rn(v);
    lo = __float2half_rn(v - __half2float(hi));
}

// ============ split-fp16 tensor-core GEMM, double-buffered ============
// C[M,N] = A·B^T + bias. Columns < n3 -> 3 products, else 2 (drop AlBh).
// B fragments loaded via x4 ldmatrix (2 n-tiles per instruction).
#define A_OFF(s,r,c) ((s)*128*40 + (r)*40 + (c))
#define B_OFF(s,r,c) ((s)*64*40 + (r)*40 + (c))
#define GEMM_SMEM (2*(2*128*40 + 2*64*40) * 2)   // 61440 bytes

__global__ void __launch_bounds__(256, 2) gemm_kernel(
    const __half* __restrict__ Ah, const __half* __restrict__ Al,
    const __half* __restrict__ Bh, const __half* __restrict__ Bl,
    const float* __restrict__ bias, float* __restrict__ C, int N, int K, int n3)
{
    extern __shared__ __half sm[];
    __half* sAh = sm;
    __half* sAl = sAh + 2*128*40;
    __half* sBh = sAl + 2*128*40;
    __half* sBl = sBh + 2*64*40;

    int tid = threadIdx.x;
    int warp = tid >> 5, lane = tid & 31;
    int wm = warp >> 1, wn = warp & 1;
    int row0 = blockIdx.y * 128, col0 = blockIdx.x * 64;
    bool full3 = (col0 < n3);

    float acc[2][4][4];
#pragma unroll
    for (int mi = 0; mi < 2; mi++)
#pragma unroll
        for (int j = 0; j < 4; j++)
#pragma unroll
            for (int r = 0; r < 4; r++) acc[mi][j][r] = 0.f;

#define STAGE(kc, s) do { \
    int k0 = (kc) << 5; \
    _Pragma("unroll") \
    for (int i = 0; i < 2; i++) { \
        int e = tid + i * 256; \
        int r = e >> 2, cs = (e & 3) * 8; \
        size_t ga = (size_t)(row0 + r) * K + k0 + cs; \
        cp16(smem_u32(&sAh[A_OFF(s, r, cs)]), Ah + ga); \
        cp16(smem_u32(&sAl[A_OFF(s, r, cs)]), Al + ga); \
    } \
    { int r = tid >> 2, cs = (tid & 3) * 8; \
      size_t gb = (size_t)(col0 + r) * K + k0 + cs; \
      cp16(smem_u32(&sBh[B_OFF(s, r, cs)]), Bh + gb); \
      cp16(smem_u32(&sBl[B_OFF(s, r, cs)]), Bl + gb); } \
} while (0)

    int nk = K >> 5;
    STAGE(0, 0);
    CP_COMMIT();
    for (int kc = 0; kc < nk; kc++) {
        int cur = kc & 1;
        if (kc + 1 < nk) { STAGE(kc + 1, cur ^ 1); CP_COMMIT(); CP_WAIT1(); }
        else             { CP_WAIT0(); }
        __syncthreads();

#pragma unroll
        for (int ks = 0; ks < 2; ks++) {
            uint32_t aH[2][4], aL[2][4], bH[4][2], bL[4][2];
#pragma unroll
            for (int mi = 0; mi < 2; mi++) {
                int rowa = wm * 32 + mi * 16 + (lane & 15);
                int cola = ks * 16 + (lane >> 4) * 8;
                LDSM_X4(aH[mi], smem_u32(&sAh[A_OFF(cur, rowa, cola)]));
                LDSM_X4(aL[mi], smem_u32(&sAl[A_OFF(cur, rowa, cola)]));
            }
            // B via x4: lanes 0-15 -> n-tile jp*2, lanes 16-31 -> jp*2+1
#pragma unroll
            for (int jp = 0; jp < 2; jp++) {
                int rowb = wn * 32 + jp * 16 + ((lane >> 4) & 1) * 8 + (lane & 7);
                int colb = ks * 16 + ((lane >> 3) & 1) * 8;
                uint32_t t4[4];
                LDSM_X4(t4, smem_u32(&sBh[B_OFF(cur, rowb, colb)]));
                bH[jp*2][0] = t4[0]; bH[jp*2][1] = t4[1];
                bH[jp*2+1][0] = t4[2]; bH[jp*2+1][1] = t4[3];
                LDSM_X4(t4, smem_u32(&sBl[B_OFF(cur, rowb, colb)]));
                bL[jp*2][0] = t4[0]; bL[jp*2][1] = t4[1];
                bL[jp*2+1][0] = t4[2]; bL[jp*2+1][1] = t4[3];
            }
#pragma unroll
            for (int mi = 0; mi < 2; mi++)
#pragma unroll
                for (int j = 0; j < 4; j++) {
                    MMA16816(acc[mi][j], aH[mi], bH[j]);
                    MMA16816(acc[mi][j], aH[mi], bL[j]);
                }
            if (full3) {
#pragma unroll
                for (int mi = 0; mi < 2; mi++)
#pragma unroll
                    for (int j = 0; j < 4; j++)
                        MMA16816(acc[mi][j], aL[mi], bH[j]);
            }
        }
        __syncthreads();
    }
#undef STAGE

    int g = lane >> 2, t = lane & 3;
#pragma unroll
    for (int mi = 0; mi < 2; mi++)
#pragma unroll
        for (int j = 0; j < 4; j++) {
            int col = col0 + wn * 32 + j * 8 + t * 2;
            float2 bv = *reinterpret_cast<const float2*>(&bias[col]);
            int r0 = row0 + wm * 32 + mi * 16 + g;
            float2 o0 = make_float2(acc[mi][j][0] + bv.x, acc[mi][j][1] + bv.y);
            float2 o1 = make_float2(acc[mi][j][2] + bv.x, acc[mi][j][3] + bv.y);
            *reinterpret_cast<float2*>(&C[(size_t)r0 * N + col]) = o0;
            *reinterpret_cast<float2*>(&C[(size_t)(r0 + 8) * N + col]) = o1;
        }
}

// ============ fused offset/mask GEMM: im2col gather + split-fp16 MMA ========
__global__ void __launch_bounds__(256, 2) offmask_gemm_kernel()
{
    __shared__ __half sAh[128*40], sAl[128*40], sBh[64*40], sBl[64*40];
    int tid = threadIdx.x;
    int warp = tid >> 5, lane = tid & 31;
    int wm = warp >> 1, wn = warp & 1;
    int row0 = blockIdx.y * 128, col0 = blockIdx.x * 64;
    int b = row0 >> 12;
    int hbase = (row0 & 4095) >> 6;

    float acc[2][4][4];
#pragma unroll
    for (int mi = 0; mi < 2; mi++)
#pragma unroll
        for (int j = 0; j < 4; j++)
#pragma unroll
            for (int r = 0; r < 4; r++) acc[mi][j][r] = 0.f;

    for (int kc = 0; kc < NF / 32; kc++) {
        int f0 = kc << 5;
        int dy, dx, cofs;
        if (f0 < 576) { int t = f0 >> 6; dy = t / 3 - 1; dx = t % 3 - 1; cofs = f0 & 63; }
        else          { dy = 0; dx = 0; cofs = 64 + (f0 - 576); }

        __syncthreads();
#pragma unroll
        for (int i = 0; i < 4; i++) {
            int idx = tid + i * 256;
            int px = idx >> 3;
            int c4 = (idx & 7) << 2;
            int hh = hbase + (px >> 6) + dy;
            int xx = (px & 63) + dx;
            uint2 hv = make_uint2(0u, 0u), lv = make_uint2(0u, 0u);
            if (hh >= 0 && hh < HD && xx >= 0 && xx < WD) {
                size_t base = ((size_t)(b * HD + hh) * WD + xx) * CD + cofs + c4;
                hv = *reinterpret_cast<const uint2*>(&g_qh[base]);
                lv = *reinterpret_cast<const uint2*>(&g_ql[base]);
            }
            *reinterpret_cast<uint2*>(&sAh[px * 40 + c4]) = hv;
            *reinterpret_cast<uint2*>(&sAl[px * 40 + c4]) = lv;
        }
        {
            int r = tid >> 2, cs = (tid & 3) * 8;
            size_t gb = (size_t)(col0 + r) * NF + f0 + cs;
            cp16(smem_u32(&sBh[r * 40 + cs]), g_cwh + gb);
            cp16(smem_u32(&sBl[r * 40 + cs]), g_cwl + gb);
        }
        CP_COMMIT();
        CP_WAIT0();
        __syncthreads();

#pragma unroll
        for (int ks = 0; ks < 2; ks++) {
            uint32_t aH[2][4], aL[2][4], bH[4][2], bL[4][2];
#pragma unroll
            for (int mi = 0; mi < 2; mi++) {
                int rowa = wm * 32 + mi * 16 + (lane & 15);
                int cola = ks * 16 + (lane >> 4) * 8;
                LDSM_X4(aH[mi], smem_u32(&sAh[rowa * 40 + cola]));
                LDSM_X4(aL[mi], smem_u32(&sAl[rowa * 40 + cola]));
            }
#pragma unroll
            for (int jp = 0; jp < 2; jp++) {
                int rowb = wn * 32 + jp * 16 + ((lane >> 4) & 1) * 8 + (lane & 7);
                int colb = ks * 16 + ((lane >> 3) & 1) * 8;
                uint32_t t4[4];
                LDSM_X4(t4, smem_u32(&sBh[rowb * 40 + colb]));
                bH[jp*2][0] = t4[0]; bH[jp*2][1] = t4[1];
                bH[jp*2+1][0] = t4[2]; bH[jp*2+1][1] = t4[3];
                LDSM_X4(t4, smem_u32(&sBl[rowb * 40 + colb]));
                bL[jp*2][0] = t4[0]; bL[jp*2][1] = t4[1];
                bL[jp*2+1][0] = t4[2]; bL[jp*2+1][1] = t4[3];
            }
#pragma unroll
            for (int mi = 0; mi < 2; mi++)
#pragma unroll
                for (int j = 0; j < 4; j++) {
                    MMA16816(acc[mi][j], aH[mi], bH[j]);
                    MMA16816(acc[mi][j], aH[mi], bL[j]);
                    MMA16816(acc[mi][j], aL[mi], bH[j]);
                }
        }
    }

    int g = lane >> 2, t = lane & 3;
#pragma unroll
    for (int mi = 0; mi < 2; mi++)
#pragma unroll
        for (int j = 0; j < 4; j++) {
            int col = col0 + wn * 32 + j * 8 + t * 2;
            float2 bv = *reinterpret_cast<const float2*>(&g_combB[col]);
            int r0 = row0 + wm * 32 + mi * 16 + g;
            float2 o0 = make_float2(acc[mi][j][0] + bv.x, acc[mi][j][1] + bv.y);
            float2 o1 = make_float2(acc[mi][j][2] + bv.x, acc[mi][j][3] + bv.y);
            *reinterpret_cast<float2*>(&g_offmask[(size_t)r0 * NOP + col]) = o0;
            *reinterpret_cast<float2*>(&g_offmask[(size_t)(r0 + 8) * NOP + col]) = o1;
        }
}

// ------- conversions: weights (transpose+split) -------
__global__ void __launch_bounds__(256) convert_w_kernel(
    const float* __restrict__ qkv_w, const float* __restrict__ proj_w)
{
    int bid = blockIdx.x, tid = threadIdx.x;
    if (bid < C3) {
        int o = bid;
        __half h, l; split1(qkv_w[(size_t)tid * C3 + o], h, l);
        g_qwh[(size_t)o * CD + tid] = h;
        g_qwl[(size_t)o * CD + tid] = l;
    } else {
        int o = bid - C3;
        __half h, l; split1(proj_w[(size_t)tid * CD + o], h, l);
        g_pwh[(size_t)o * CD + tid] = h;
        g_pwl[(size_t)o * CD + tid] = l;
    }
}

// ------- conversions: x split -------
__global__ void __launch_bounds__(256) convert_x_kernel(const float* __restrict__ x)
{
    int i = (blockIdx.x * 256 + threadIdx.x) * 4;
    float4 v = *reinterpret_cast<const float4*>(&x[i]);
    float f[4] = {v.x, v.y, v.z, v.w};
#pragma unroll
    for (int j = 0; j < 4; j++) {
        __half h, l; split1(f[j], h, l);
        g_xhi[i + j] = h; g_xlo[i + j] = l;
    }
}

// ---------------- depthwise 3x3, 4 px/thread; q hi/lo fp16, kv float2 -----
__global__ void __launch_bounds__(192) dwconv_kernel(
    const float* __restrict__ in, const float* __restrict__ w,
    const float* __restrict__ bias)
{
    int c = threadIdx.x * 4;
    int x0 = blockIdx.x * 4, y = blockIdx.y, b = blockIdx.z;
    float4 bz = *reinterpret_cast<const float4*>(&bias[c]);
    float4 acc[4] = {bz, bz, bz, bz};
#pragma unroll
    for (int ky = 0; ky < 3; ky++) {
        int yy = y + ky - 1;
        if (yy < 0 || yy >= HD) continue;
        const float* rowp = in + ((size_t)(b * HD + yy) * WD) * C3 + c;
        float4 iv[6];
#pragma unroll
        for (int j = 0; j < 6; j++) {
            int xx = x0 - 1 + j;
            iv[j] = (xx >= 0 && xx < WD)
                ? *reinterpret_cast<const float4*>(rowp + (size_t)xx * C3)
                : make_float4(0.f, 0.f, 0.f, 0.f);
        }
#pragma unroll
        for (int kx = 0; kx < 3; kx++) {
            float4 wv = *reinterpret_cast<const float4*>(&w[(ky * 3 + kx) * C3 + c]);
#pragma unroll
            for (int p = 0; p < 4; p++) {
                acc[p].x += wv.x * iv[p + kx].x; acc[p].y += wv.y * iv[p + kx].y;
                acc[p].z += wv.z * iv[p + kx].z; acc[p].w += wv.w * iv[p + kx].w;
            }
        }
    }
#pragma unroll
    for (int p = 0; p < 4; p++) {
        size_t pix = (size_t)(b * HD + y) * WD + x0 + p;
        if (c < CD) {
            __half h0,h1,h2,h3,l0,l1,l2,l3;
            split1(acc[p].x,h0,l0); split1(acc[p].y,h1,l1);
            split1(acc[p].z,h2,l2); split1(acc[p].w,h3,l3);
            size_t o = pix * CD + c;
            *reinterpret_cast<__half2*>(&g_qh[o])   = __halves2half2(h0,h1);
            *reinterpret_cast<__half2*>(&g_qh[o+2]) = __halves2half2(h2,h3);
            *reinterpret_cast<__half2*>(&g_ql[o])   = __halves2half2(l0,l1);
            *reinterpret_cast<__half2*>(&g_ql[o+2]) = __halves2half2(l2,l3);
        } else if (c < 2 * CD) {
            float2* bp = &g_kv[pix * CD + (c - CD)];
            bp[0].x = acc[p].x; bp[1].x = acc[p].y;
            bp[2].x = acc[p].z; bp[3].x = acc[p].w;
        } else {
            float2* bp = &g_kv[pix * CD + (c - 2 * CD)];
            bp[0].y = acc[p].x; bp[1].y = acc[p].y;
            bp[2].y = acc[p].z; bp[3].y = acc[p].w;
        }
    }
}

// ---------------- fold pconv+proj -> combW^T hi/lo + bias ----------------
__global__ void __launch_bounds__(128) prep_kernel(
    const float* __restrict__ off_pconv_w, const float* __restrict__ off_w,
    const float* __restrict__ off_b, const float* __restrict__ mask_pconv_w,
    const float* __restrict__ mask_w, const float* __restrict__ mask_b)
{
    int o = blockIdx.x;
    int f = blockIdx.y * 128 + threadIdx.x;
    if (o >= 153) {
        g_cwh[(size_t)o * NF + f] = __float2half_rn(0.f);
        g_cwl[(size_t)o * NF + f] = __float2half_rn(0.f);
        if (threadIdx.x == 0 && blockIdx.y == 0) g_combB[o] = 0.f;
        return;
    }
    bool is_mask = (o >= 144);
    int g = 0, j = 0, kk = 0;
    if (!is_mask) { g = o / 18; j = o % 18; } else { kk = o - 144; }

    float s;
    if (f < 576) {
        int t = f >> 6, ic = f & 63;
        s = 0.f;
        if (!is_mask) {
            const float* ow = off_w + (g * 18 + j) * 256;
            const float* pc = off_pconv_w + ((size_t)(g * 64) * 64 + ic) * 9 + t;
#pragma unroll 4
            for (int oc = 0; oc < 64; oc++) s += ow[oc] * pc[(size_t)oc * 64 * 9];
        } else {
            const float* mw = mask_w + kk * 256;
            const float* pc = mask_pconv_w + (size_t)ic * 9 + t;
#pragma unroll 4
            for (int oc = 0; oc < 64; oc++) s += mw[oc] * pc[(size_t)oc * 64 * 9];
        }
    } else {
        int ch = f - 512;
        s = is_mask ? mask_w[kk * 256 + ch] : off_w[(g * 18 + j) * 256 + ch];
    }
    __half h, l; split1(s, h, l);
    g_cwh[(size_t)o * NF + f] = h;
    g_cwl[(size_t)o * NF + f] = l;
    if (threadIdx.x == 0 && blockIdx.y == 0)
        g_combB[o] = is_mask ? mask_b[kk]
                             : (off_b[g * 18 + j] + c_PTS[j] * (float)(2 * g + 1));
}

// ---------------- deformable attention: warp per (b,g,pixel) --------------
__global__ void __launch_bounds__(256) attn_kernel()
{
    int warp = threadIdx.x >> 5, lane = threadIdx.x & 31;
    int px = blockIdx.x * 8 + warp;
    int g = blockIdx.y, b = blockIdx.z;
    int h = px >> 6, w = px & 63;

    const float* om = g_offmask + ((size_t)(b * HD + h) * WD + w) * NOP;
    size_t qi = ((size_t)(b * HD + h) * WD + w) * CD + g * HCD + lane;
    float qv = (__half2float(g_qh[qi]) + __half2float(g_ql[qi]))
             * 0.17677669529663687f;

    float attn[KP], vk[KP];
#pragma unroll
    for (int k = 0; k < KP; k++) {
        float ox = om[g * 18 + 2 * k], oy = om[g * 18 + 2 * k + 1], mk = om[144 + k];
        float cx = fminf(fmaxf((float)w + ox, 0.f), (float)(WD - 1));
        float cy = fminf(fmaxf((float)h + oy, 0.f), (float)(HD - 1));
        float x0f = floorf(cx), y0f = floorf(cy);
        float fx = cx - x0f, fy = cy - y0f;
        int x0 = (int)x0f, y0 = (int)y0f;
        int x1 = min(x0 + 1, WD - 1), y1 = min(y0 + 1, HD - 1);
        size_t i00 = ((size_t)(b * HD + y0) * WD + x0) * CD + g * HCD + lane;
        size_t i01 = ((size_t)(b * HD + y0) * WD + x1) * CD + g * HCD + lane;
        size_t i10 = ((size_t)(b * HD + y1) * WD + x0) * CD + g * HCD + lane;
        size_t i11 = ((size_t)(b * HD + y1) * WD + x1) * CD + g * HCD + lane;
        float2 kv00 = g_kv[i00], kv01 = g_kv[i01];
        float2 kv10 = g_kv[i10], kv11 = g_kv[i11];
        float w00 = (1.f - fx) * (1.f - fy), w01 = fx * (1.f - fy);
        float w10 = (1.f - fx) * fy,         w11 = fx * fy;
        float kvv = kv00.x*w00 + kv01.x*w01 + kv10.x*w10 + kv11.x*w11;
        float vvv = kv00.y*w00 + kv01.y*w01 + kv10.y*w10 + kv11.y*w11;
        kvv *= mk; vvv *= mk;
        float d = qv * kvv;
#pragma unroll
        for (int s = 16; s; s >>= 1) d += __shfl_xor_sync(0xffffffffu, d, s);
        attn[k] = d;
        vk[k] = vvv;
    }
    float m = attn[0];
#pragma unroll
    for (int k = 1; k < KP; k++) m = fmaxf(m, attn[k]);
    float ssum = 0.f, o = 0.f;
#pragma unroll
    for (int k = 0; k < KP; k++) {
        float e = __expf(attn[k] - m);
        ssum += e;
        o += e * vk[k];
    }
    o /= ssum;
    size_t oi = ((size_t)((b * HD + h) * WD + w)) * CD + g * HCD + lane;
    __half hh, ll; split1(o, hh, ll);
    g_aoh[oi] = hh; g_aol[oi] = ll;
}

// --------------------------------- launch ---------------------------------
extern "C" void kernel_launch(void* const* d_in, const int* in_sizes, int n_in,
                              void* d_out, int out_size)
{
    const float* x            = (const float*)d_in[0];
    const float* qkv_w        = (const float*)d_in[1];
    const float* qkv_b        = (const float*)d_in[2];
    const float* dw_w         = (const float*)d_in[3];
    const float* dw_b         = (const float*)d_in[4];
    const float* off_pconv_w  = (const float*)d_in[5];
    const float* off_w        = (const float*)d_in[6];
    const float* off_b        = (const float*)d_in[7];
    const float* mask_pconv_w = (const float*)d_in[8];
    const float* mask_w       = (const float*)d_in[9];
    const float* mask_b       = (const float*)d_in[10];
    const float* proj_w       = (const float*)d_in[11];
    const float* proj_b       = (const float*)d_in[12];
    float* out = (float*)d_out;

    cudaFuncSetAttribute(gemm_kernel,
                         cudaFuncAttributeMaxDynamicSharedMemorySize, GEMM_SMEM);

    __half *xh, *xl, *qwh, *qwl, *pwh, *pwl, *aoh, *aol;
    float *qkv;
    cudaGetSymbolAddress((void**)&xh, g_xhi);   cudaGetSymbolAddress((void**)&xl, g_xlo);
    cudaGetSymbolAddress((void**)&qwh, g_qwh);  cudaGetSymbolAddress((void**)&qwl, g_qwl);
    cudaGetSymbolAddress((void**)&pwh, g_pwh);  cudaGetSymbolAddress((void**)&pwl, g_pwl);
    cudaGetSymbolAddress((void**)&aoh, g_aoh);  cudaGetSymbolAddress((void**)&aol, g_aol);
    cudaGetSymbolAddress((void**)&qkv, g_qkv);

    // launch order chosen so the ncu capture slot (#4) lands on the qkv GEMM
    convert_w_kernel<<<C3 + CD, 256>>>(qkv_w, proj_w);                     // 1
    {
        dim3 grid(NOP, NF / 128);
        prep_kernel<<<grid, 128>>>(off_pconv_w, off_w, off_b,
                                   mask_pconv_w, mask_w, mask_b);          // 2
    }
    convert_x_kernel<<<(MR * CD) / 1024, 256>>>(x);                        // 3
    {
        dim3 grid(C3 / 64, MR / 128);
        gemm_kernel<<<grid, 256, GEMM_SMEM>>>(xh, xl, qwh, qwl, qkv_b, qkv,
                                              C3, CD, CD);                 // 4 (profiled)
    }
    {
        dim3 grid(WD / 4, HD, BD);
        dwconv_kernel<<<grid, 192>>>(qkv, dw_w, dw_b);                     // 5
    }
    {
        dim3 grid(NOP / 64, MR / 128);
        offmask_gemm_kernel<<<grid, 256>>>();                              // 6
    }
    {
        dim3 grid(PD / 8, GD, BD);
        attn_kernel<<<grid, 256>>>();                                      // 7
    }
    {
        dim3 grid(CD / 64, MR / 128);
        gemm_kernel<<<grid, 256, GEMM_SMEM>>>(aoh, aol, pwh, pwl, proj_b, out,
                                              CD, CD, 0);                  // 8
    }
}

// round 12
// speedup vs baseline: 1.1086x; 1.0302x over previous
#include <cuda_runtime.h>
#include <cuda_fp16.h>
#include <cstdint>

#define BD 2
#define HD 64
#define WD 64
#define CD 256
#define GD 8
#define KP 9
#define HCD 32
#define PD (HD*WD)
#define C3 (3*CD)
#define NOP 192
#define NF 768
#define MR (BD*PD)

// ---------------- scratch ----------------
__device__ float  g_qkv[MR*C3];
__device__ __half g_qh[MR*CD], g_ql[MR*CD];
__device__ float2 g_kv[MR*CD];
__device__ float  g_offmask[MR*NOP];
__device__ float  g_combB[NOP];
__device__ __half g_xhi[MR*CD], g_xlo[MR*CD];
__device__ __half g_qwh[C3*CD], g_qwl[C3*CD];
__device__ __half g_pwh[CD*CD], g_pwl[CD*CD];
__device__ __half g_cwh[NOP*NF], g_cwl[NOP*NF];
__device__ __half g_aoh[MR*CD], g_aol[MR*CD];

__constant__ float c_PTS[18] = {-1,-1,-1,0,-1,1,0,-1,0,0,0,1,1,-1,1,0,1,1};

// ---------------- helpers ----------------
__device__ __forceinline__ uint32_t smem_u32(const void* p) {
    uint32_t a;
    asm("{ .reg .u64 t; cvta.to.shared.u64 t, %1; cvt.u32.u64 %0, t; }" : "=r"(a) : "l"(p));
    return a;
}
__device__ __forceinline__ void cp16(uint32_t dst, const void* src) {
    asm volatile("cp.async.cg.shared.global [%0], [%1], 16;" :: "r"(dst), "l"(src));
}
#define CP_COMMIT() asm volatile("cp.async.commit_group;" ::: "memory")
#define CP_WAIT0()  asm volatile("cp.async.wait_group 0;" ::: "memory")
#define CP_WAIT1()  asm volatile("cp.async.wait_group 1;" ::: "memory")
#define LDSM_X4(r, a) asm volatile( \
    "ldmatrix.sync.aligned.m8n8.x4.shared.b16 {%0,%1,%2,%3}, [%4];" \
    : "=r"((r)[0]),"=r"((r)[1]),"=r"((r)[2]),"=r"((r)[3]) : "r"(a))
#define MMA16816(c, a, b) asm volatile( \
    "mma.sync.aligned.m16n8k16.row.col.f32.f16.f16.f32 " \
    "{%0,%1,%2,%3}, {%4,%5,%6,%7}, {%8,%9}, {%0,%1,%2,%3};" \
    : "+f"((c)[0]),"+f"((c)[1]),"+f"((c)[2]),"+f"((c)[3]) \
    : "r"((a)[0]),"r"((a)[1]),"r"((a)[2]),"r"((a)[3]), "r"((b)[0]),"r"((b)[1]))

__device__ __forceinline__ void split1(float v, __half& hi, __half& lo) {
    hi = __float2half_rn(v);
    lo = __float2half_rn(v - __half2float(hi));
}

// ============ split-fp16 GEMM, 3-stage pipeline, 1 sync/chunk ============
// C[M,N] = A·B^T + bias. Columns < n3 -> 3 products, else 2.
#define AT 5120                        // 128*40 halves per A stage
#define BT 2560                        // 64*40 halves per B stage
#define GEMM_SMEM ((3*AT*2 + 3*BT*2) * 2)   // 92160 bytes

__global__ void __launch_bounds__(256, 2) gemm_kernel(
    const __half* __restrict__ Ah, const __half* __restrict__ Al,
    const __half* __restrict__ Bh, const __half* __restrict__ Bl,
    const float* __restrict__ bias, float* __restrict__ C, int N, int K, int n3)
{
    extern __shared__ __half sm[];
    __half* sAh = sm;                 // [3][128][40]
    __half* sAl = sAh + 3*AT;
    __half* sBh = sAl + 3*AT;         // [3][64][40]
    __half* sBl = sBh + 3*BT;

    int tid = threadIdx.x;
    int warp = tid >> 5, lane = tid & 31;
    int wm = warp >> 1, wn = warp & 1;
    int row0 = blockIdx.y * 128, col0 = blockIdx.x * 64;
    bool full3 = (col0 < n3);

    float acc[2][4][4];
#pragma unroll
    for (int mi = 0; mi < 2; mi++)
#pragma unroll
        for (int j = 0; j < 4; j++)
#pragma unroll
            for (int r = 0; r < 4; r++) acc[mi][j][r] = 0.f;

#define STAGE(kc, s) do { \
    int k0 = (kc) << 5; \
    _Pragma("unroll") \
    for (int i = 0; i < 2; i++) { \
        int e = tid + i * 256; \
        int r = e >> 2, cs = (e & 3) * 8; \
        size_t ga = (size_t)(row0 + r) * K + k0 + cs; \
        cp16(smem_u32(&sAh[(s)*AT + r*40 + cs]), Ah + ga); \
        cp16(smem_u32(&sAl[(s)*AT + r*40 + cs]), Al + ga); \
    } \
    { int r = tid >> 2, cs = (tid & 3) * 8; \
      size_t gb = (size_t)(col0 + r) * K + k0 + cs; \
      cp16(smem_u32(&sBh[(s)*BT + r*40 + cs]), Bh + gb); \
      cp16(smem_u32(&sBl[(s)*BT + r*40 + cs]), Bl + gb); } \
} while (0)

    int nk = K >> 5;
    STAGE(0, 0); CP_COMMIT();
    if (nk > 1) { STAGE(1, 1); CP_COMMIT(); }

    int cur = 0, nxt2 = 2;
    for (int kc = 0; kc < nk; kc++) {
        if (kc + 1 < nk) CP_WAIT1(); else CP_WAIT0();
        __syncthreads();
        if (kc + 2 < nk) {
            STAGE(kc + 2, nxt2);
            CP_COMMIT();
            nxt2 = (nxt2 == 2) ? 0 : nxt2 + 1;
        }
        // preload fragments for both ks steps, then MMA
        uint32_t aH[2][2][4], aL[2][2][4], bH[2][4][2], bL[2][4][2];
#pragma unroll
        for (int ks = 0; ks < 2; ks++) {
#pragma unroll
            for (int mi = 0; mi < 2; mi++) {
                int rowa = wm * 32 + mi * 16 + (lane & 15);
                int cola = ks * 16 + (lane >> 4) * 8;
                LDSM_X4(aH[ks][mi], smem_u32(&sAh[cur*AT + rowa*40 + cola]));
                LDSM_X4(aL[ks][mi], smem_u32(&sAl[cur*AT + rowa*40 + cola]));
            }
#pragma unroll
            for (int jp = 0; jp < 2; jp++) {
                int rowb = wn * 32 + jp * 16 + ((lane >> 4) & 1) * 8 + (lane & 7);
                int colb = ks * 16 + ((lane >> 3) & 1) * 8;
                uint32_t t4[4];
                LDSM_X4(t4, smem_u32(&sBh[cur*BT + rowb*40 + colb]));
                bH[ks][jp*2][0] = t4[0]; bH[ks][jp*2][1] = t4[1];
                bH[ks][jp*2+1][0] = t4[2]; bH[ks][jp*2+1][1] = t4[3];
                LDSM_X4(t4, smem_u32(&sBl[cur*BT + rowb*40 + colb]));
                bL[ks][jp*2][0] = t4[0]; bL[ks][jp*2][1] = t4[1];
                bL[ks][jp*2+1][0] = t4[2]; bL[ks][jp*2+1][1] = t4[3];
            }
        }
#pragma unroll
        for (int ks = 0; ks < 2; ks++) {
#pragma unroll
            for (int mi = 0; mi < 2; mi++)
#pragma unroll
                for (int j = 0; j < 4; j++) {
                    MMA16816(acc[mi][j], aH[ks][mi], bH[ks][j]);
                    MMA16816(acc[mi][j], aH[ks][mi], bL[ks][j]);
                }
            if (full3) {
#pragma unroll
                for (int mi = 0; mi < 2; mi++)
#pragma unroll
                    for (int j = 0; j < 4; j++)
                        MMA16816(acc[mi][j], aL[ks][mi], bH[ks][j]);
            }
        }
        cur = (cur == 2) ? 0 : cur + 1;
    }
#undef STAGE

    int g = lane >> 2, t = lane & 3;
#pragma unroll
    for (int mi = 0; mi < 2; mi++)
#pragma unroll
        for (int j = 0; j < 4; j++) {
            int col = col0 + wn * 32 + j * 8 + t * 2;
            float2 bv = *reinterpret_cast<const float2*>(&bias[col]);
            int r0 = row0 + wm * 32 + mi * 16 + g;
            float2 o0 = make_float2(acc[mi][j][0] + bv.x, acc[mi][j][1] + bv.y);
            float2 o1 = make_float2(acc[mi][j][2] + bv.x, acc[mi][j][3] + bv.y);
            *reinterpret_cast<float2*>(&C[(size_t)r0 * N + col]) = o0;
            *reinterpret_cast<float2*>(&C[(size_t)(r0 + 8) * N + col]) = o1;
        }
}

// ============ fused offset/mask GEMM: double-buffered, reg-staged gather ====
#define OM_SMEM ((2*AT*2 + 2*BT*2) * 2)   // 61440 bytes

__device__ __forceinline__ void om_gather(
    int kc, int b, int hbase, int tid, uint2* hv, uint2* lv)
{
    int f0 = kc << 5;
    int dy, dx, cofs;
    if (f0 < 576) { int t = f0 >> 6; dy = t / 3 - 1; dx = t % 3 - 1; cofs = f0 & 63; }
    else          { dy = 0; dx = 0; cofs = 64 + (f0 - 576); }
#pragma unroll
    for (int i = 0; i < 4; i++) {
        int idx = tid + i * 256;
        int px = idx >> 3;
        int c4 = (idx & 7) << 2;
        int hh = hbase + (px >> 6) + dy;
        int xx = (px & 63) + dx;
        hv[i] = make_uint2(0u, 0u); lv[i] = make_uint2(0u, 0u);
        if (hh >= 0 && hh < HD && xx >= 0 && xx < WD) {
            size_t base = ((size_t)(b * HD + hh) * WD + xx) * CD + cofs + c4;
            hv[i] = *reinterpret_cast<const uint2*>(&g_qh[base]);
            lv[i] = *reinterpret_cast<const uint2*>(&g_ql[base]);
        }
    }
}

__global__ void __launch_bounds__(256, 2) offmask_gemm_kernel()
{
    extern __shared__ __half sm[];
    __half* sAh = sm;                 // [2][128][40]
    __half* sAl = sAh + 2*AT;
    __half* sBh = sAl + 2*AT;         // [2][64][40]
    __half* sBl = sBh + 2*BT;

    int tid = threadIdx.x;
    int warp = tid >> 5, lane = tid & 31;
    int wm = warp >> 1, wn = warp & 1;
    int row0 = blockIdx.y * 128, col0 = blockIdx.x * 64;
    int b = row0 >> 12;
    int hbase = (row0 & 4095) >> 6;

    float acc[2][4][4];
#pragma unroll
    for (int mi = 0; mi < 2; mi++)
#pragma unroll
        for (int j = 0; j < 4; j++)
#pragma unroll
            for (int r = 0; r < 4; r++) acc[mi][j][r] = 0.f;

#define OM_STS(s) do { \
    _Pragma("unroll") \
    for (int i = 0; i < 4; i++) { \
        int idx = tid + i * 256; \
        int px = idx >> 3, c4 = (idx & 7) << 2; \
        *reinterpret_cast<uint2*>(&sAh[(s)*AT + px*40 + c4]) = hv[i]; \
        *reinterpret_cast<uint2*>(&sAl[(s)*AT + px*40 + c4]) = lv[i]; \
    } \
} while (0)
#define OM_CPB(kc, s) do { \
    int r = tid >> 2, cs = (tid & 3) * 8; \
    size_t gb = (size_t)(col0 + r) * NF + ((kc) << 5) + cs; \
    cp16(smem_u32(&sBh[(s)*BT + r*40 + cs]), g_cwh + gb); \
    cp16(smem_u32(&sBl[(s)*BT + r*40 + cs]), g_cwl + gb); \
} while (0)

    const int NK = NF / 32;            // 24
    uint2 hv[4], lv[4];
    om_gather(0, b, hbase, tid, hv, lv);
    OM_STS(0);
    OM_CPB(0, 0);
    CP_COMMIT();
    om_gather(1, b, hbase, tid, hv, lv);   // prefetch chunk 1 into regs

    for (int kc = 0; kc < NK; kc++) {
        int cur = kc & 1;
        CP_WAIT0();
        __syncthreads();
        if (kc + 1 < NK) {
            OM_STS(cur ^ 1);               // A(kc+1) regs -> other buffer
            OM_CPB(kc + 1, cur ^ 1);
            CP_COMMIT();
        }
        if (kc + 2 < NK)
            om_gather(kc + 2, b, hbase, tid, hv, lv);   // LDG overlaps MMAs

#pragma unroll
        for (int ks = 0; ks < 2; ks++) {
            uint32_t aH[2][4], aL[2][4], bH[4][2], bL[4][2];
#pragma unroll
            for (int mi = 0; mi < 2; mi++) {
                int rowa = wm * 32 + mi * 16 + (lane & 15);
                int cola = ks * 16 + (lane >> 4) * 8;
                LDSM_X4(aH[mi], smem_u32(&sAh[cur*AT + rowa*40 + cola]));
                LDSM_X4(aL[mi], smem_u32(&sAl[cur*AT + rowa*40 + cola]));
            }
#pragma unroll
            for (int jp = 0; jp < 2; jp++) {
                int rowb = wn * 32 + jp * 16 + ((lane >> 4) & 1) * 8 + (lane & 7);
                int colb = ks * 16 + ((lane >> 3) & 1) * 8;
                uint32_t t4[4];
                LDSM_X4(t4, smem_u32(&sBh[cur*BT + rowb*40 + colb]));
                bH[jp*2][0] = t4[0]; bH[jp*2][1] = t4[1];
                bH[jp*2+1][0] = t4[2]; bH[jp*2+1][1] = t4[3];
                LDSM_X4(t4, smem_u32(&sBl[cur*BT + rowb*40 + colb]));
                bL[jp*2][0] = t4[0]; bL[jp*2][1] = t4[1];
                bL[jp*2+1][0] = t4[2]; bL[jp*2+1][1] = t4[3];
            }
#pragma unroll
            for (int mi = 0; mi < 2; mi++)
#pragma unroll
                for (int j = 0; j < 4; j++) {
                    MMA16816(acc[mi][j], aH[mi], bH[j]);
                    MMA16816(acc[mi][j], aH[mi], bL[j]);
                    MMA16816(acc[mi][j], aL[mi], bH[j]);
                }
        }
    }
#undef OM_STS
#undef OM_CPB

    int g = lane >> 2, t = lane & 3;
#pragma unroll
    for (int mi = 0; mi < 2; mi++)
#pragma unroll
        for (int j = 0; j < 4; j++) {
            int col = col0 + wn * 32 + j * 8 + t * 2;
            float2 bv = *reinterpret_cast<const float2*>(&g_combB[col]);
            int r0 = row0 + wm * 32 + mi * 16 + g;
            float2 o0 = make_float2(acc[mi][j][0] + bv.x, acc[mi][j][1] + bv.y);
            float2 o1 = make_float2(acc[mi][j][2] + bv.x, acc[mi][j][3] + bv.y);
            *reinterpret_cast<float2*>(&g_offmask[(size_t)r0 * NOP + col]) = o0;
            *reinterpret_cast<float2*>(&g_offmask[(size_t)(r0 + 8) * NOP + col]) = o1;
        }
}

// ------- conversions: weights -------
__global__ void __launch_bounds__(256) convert_w_kernel(
    const float* __restrict__ qkv_w, const float* __restrict__ proj_w)
{
    int bid = blockIdx.x, tid = threadIdx.x;
    if (bid < C3) {
        int o = bid;
        __half h, l; split1(qkv_w[(size_t)tid * C3 + o], h, l);
        g_qwh[(size_t)o * CD + tid] = h;
        g_qwl[(size_t)o * CD + tid] = l;
    } else {
        int o = bid - C3;
        __half h, l; split1(proj_w[(size_t)tid * CD + o], h, l);
        g_pwh[(size_t)o * CD + tid] = h;
        g_pwl[(size_t)o * CD + tid] = l;
    }
}

// ------- conversions: x -------
__global__ void __launch_bounds__(256) convert_x_kernel(const float* __restrict__ x)
{
    int i = (blockIdx.x * 256 + threadIdx.x) * 4;
    float4 v = *reinterpret_cast<const float4*>(&x[i]);
    float f[4] = {v.x, v.y, v.z, v.w};
#pragma unroll
    for (int j = 0; j < 4; j++) {
        __half h, l; split1(f[j], h, l);
        g_xhi[i + j] = h; g_xlo[i + j] = l;
    }
}

// ---------------- depthwise 3x3 ----------------
__global__ void __launch_bounds__(192) dwconv_kernel(
    const float* __restrict__ in, const float* __restrict__ w,
    const float* __restrict__ bias)
{
    int c = threadIdx.x * 4;
    int x0 = blockIdx.x * 4, y = blockIdx.y, b = blockIdx.z;
    float4 bz = *reinterpret_cast<const float4*>(&bias[c]);
    float4 acc[4] = {bz, bz, bz, bz};
#pragma unroll
    for (int ky = 0; ky < 3; ky++) {
        int yy = y + ky - 1;
        if (yy < 0 || yy >= HD) continue;
        const float* rowp = in + ((size_t)(b * HD + yy) * WD) * C3 + c;
        float4 iv[6];
#pragma unroll
        for (int j = 0; j < 6; j++) {
            int xx = x0 - 1 + j;
            iv[j] = (xx >= 0 && xx < WD)
                ? *reinterpret_cast<const float4*>(rowp + (size_t)xx * C3)
                : make_float4(0.f, 0.f, 0.f, 0.f);
        }
#pragma unroll
        for (int kx = 0; kx < 3; kx++) {
            float4 wv = *reinterpret_cast<const float4*>(&w[(ky * 3 + kx) * C3 + c]);
#pragma unroll
            for (int p = 0; p < 4; p++) {
                acc[p].x += wv.x * iv[p + kx].x; acc[p].y += wv.y * iv[p + kx].y;
                acc[p].z += wv.z * iv[p + kx].z; acc[p].w += wv.w * iv[p + kx].w;
            }
        }
    }
#pragma unroll
    for (int p = 0; p < 4; p++) {
        size_t pix = (size_t)(b * HD + y) * WD + x0 + p;
        if (c < CD) {
            __half h0,h1,h2,h3,l0,l1,l2,l3;
            split1(acc[p].x,h0,l0); split1(acc[p].y,h1,l1);
            split1(acc[p].z,h2,l2); split1(acc[p].w,h3,l3);
            size_t o = pix * CD + c;
            *reinterpret_cast<__half2*>(&g_qh[o])   = __halves2half2(h0,h1);
            *reinterpret_cast<__half2*>(&g_qh[o+2]) = __halves2half2(h2,h3);
            *reinterpret_cast<__half2*>(&g_ql[o])   = __halves2half2(l0,l1);
            *reinterpret_cast<__half2*>(&g_ql[o+2]) = __halves2half2(l2,l3);
        } else if (c < 2 * CD) {
            float2* bp = &g_kv[pix * CD + (c - CD)];
            bp[0].x = acc[p].x; bp[1].x = acc[p].y;
            bp[2].x = acc[p].z; bp[3].x = acc[p].w;
        } else {
            float2* bp = &g_kv[pix * CD + (c - 2 * CD)];
            bp[0].y = acc[p].x; bp[1].y = acc[p].y;
            bp[2].y = acc[p].z; bp[3].y = acc[p].w;
        }
    }
}

// ---------------- fold pconv+proj -> combW^T hi/lo + bias ----------------
__global__ void __launch_bounds__(128) prep_kernel(
    const float* __restrict__ off_pconv_w, const float* __restrict__ off_w,
    const float* __restrict__ off_b, const float* __restrict__ mask_pconv_w,
    const float* __restrict__ mask_w, const float* __restrict__ mask_b)
{
    int o = blockIdx.x;
    int f = blockIdx.y * 128 + threadIdx.x;
    if (o >= 153) {
        g_cwh[(size_t)o * NF + f] = __float2half_rn(0.f);
        g_cwl[(size_t)o * NF + f] = __float2half_rn(0.f);
        if (threadIdx.x == 0 && blockIdx.y == 0) g_combB[o] = 0.f;
        return;
    }
    bool is_mask = (o >= 144);
    int g = 0, j = 0, kk = 0;
    if (!is_mask) { g = o / 18; j = o % 18; } else { kk = o - 144; }

    float s;
    if (f < 576) {
        int t = f >> 6, ic = f & 63;
        s = 0.f;
        if (!is_mask) {
            const float* ow = off_w + (g * 18 + j) * 256;
            const float* pc = off_pconv_w + ((size_t)(g * 64) * 64 + ic) * 9 + t;
#pragma unroll 4
            for (int oc = 0; oc < 64; oc++) s += ow[oc] * pc[(size_t)oc * 64 * 9];
        } else {
            const float* mw = mask_w + kk * 256;
            const float* pc = mask_pconv_w + (size_t)ic * 9 + t;
#pragma unroll 4
            for (int oc = 0; oc < 64; oc++) s += mw[oc] * pc[(size_t)oc * 64 * 9];
        }
    } else {
        int ch = f - 512;
        s = is_mask ? mask_w[kk * 256 + ch] : off_w[(g * 18 + j) * 256 + ch];
    }
    __half h, l; split1(s, h, l);
    g_cwh[(size_t)o * NF + f] = h;
    g_cwl[(size_t)o * NF + f] = l;
    if (threadIdx.x == 0 && blockIdx.y == 0)
        g_combB[o] = is_mask ? mask_b[kk]
                             : (off_b[g * 18 + j] + c_PTS[j] * (float)(2 * g + 1));
}

// ---------------- deformable attention ----------------
__global__ void __launch_bounds__(256) attn_kernel()
{
    int warp = threadIdx.x >> 5, lane = threadIdx.x & 31;
    int px = blockIdx.x * 8 + warp;
    int g = blockIdx.y, b = blockIdx.z;
    int h = px >> 6, w = px & 63;

    const float* om = g_offmask + ((size_t)(b * HD + h) * WD + w) * NOP;
    size_t qi = ((size_t)(b * HD + h) * WD + w) * CD + g * HCD + lane;
    float qv = (__half2float(g_qh[qi]) + __half2float(g_ql[qi]))
             * 0.17677669529663687f;

    float attn[KP], vk[KP];
#pragma unroll
    for (int k = 0; k < KP; k++) {
        float ox = om[g * 18 + 2 * k], oy = om[g * 18 + 2 * k + 1], mk = om[144 + k];
        float cx = fminf(fmaxf((float)w + ox, 0.f), (float)(WD - 1));
        float cy = fminf(fmaxf((float)h + oy, 0.f), (float)(HD - 1));
        float x0f = floorf(cx), y0f = floorf(cy);
        float fx = cx - x0f, fy = cy - y0f;
        int x0 = (int)x0f, y0 = (int)y0f;
        int x1 = min(x0 + 1, WD - 1), y1 = min(y0 + 1, HD - 1);
        size_t i00 = ((size_t)(b * HD + y0) * WD + x0) * CD + g * HCD + lane;
        size_t i01 = ((size_t)(b * HD + y0) * WD + x1) * CD + g * HCD + lane;
        size_t i10 = ((size_t)(b * HD + y1) * WD + x0) * CD + g * HCD + lane;
        size_t i11 = ((size_t)(b * HD + y1) * WD + x1) * CD + g * HCD + lane;
        float2 kv00 = g_kv[i00], kv01 = g_kv[i01];
        float2 kv10 = g_kv[i10], kv11 = g_kv[i11];
        float w00 = (1.f - fx) * (1.f - fy), w01 = fx * (1.f - fy);
        float w10 = (1.f - fx) * fy,         w11 = fx * fy;
        float kvv = kv00.x*w00 + kv01.x*w01 + kv10.x*w10 + kv11.x*w11;
        float vvv = kv00.y*w00 + kv01.y*w01 + kv10.y*w10 + kv11.y*w11;
        kvv *= mk; vvv *= mk;
        float d = qv * kvv;
#pragma unroll
        for (int s = 16; s; s >>= 1) d += __shfl_xor_sync(0xffffffffu, d, s);
        attn[k] = d;
        vk[k] = vvv;
    }
    float m = attn[0];
#pragma unroll
    for (int k = 1; k < KP; k++) m = fmaxf(m, attn[k]);
    float ssum = 0.f, o = 0.f;
#pragma unroll
    for (int k = 0; k < KP; k++) {
        float e = __expf(attn[k] - m);
        ssum += e;
        o += e * vk[k];
    }
    o /= ssum;
    size_t oi = ((size_t)((b * HD + h) * WD + w)) * CD + g * HCD + lane;
    __half hh, ll; split1(o, hh, ll);
    g_aoh[oi] = hh; g_aol[oi] = ll;
}

// --------------------------------- launch ---------------------------------
extern "C" void kernel_launch(void* const* d_in, const int* in_sizes, int n_in,
                              void* d_out, int out_size)
{
    const float* x            = (const float*)d_in[0];
    const float* qkv_w        = (const float*)d_in[1];
    const float* qkv_b        = (const float*)d_in[2];
    const float* dw_w         = (const float*)d_in[3];
    const float* dw_b         = (const float*)d_in[4];
    const float* off_pconv_w  = (const float*)d_in[5];
    const float* off_w        = (const float*)d_in[6];
    const float* off_b        = (const float*)d_in[7];
    const float* mask_pconv_w = (const float*)d_in[8];
    const float* mask_w       = (const float*)d_in[9];
    const float* mask_b       = (const float*)d_in[10];
    const float* proj_w       = (const float*)d_in[11];
    const float* proj_b       = (const float*)d_in[12];
    float* out = (float*)d_out;

    cudaFuncSetAttribute(gemm_kernel,
                         cudaFuncAttributeMaxDynamicSharedMemorySize, GEMM_SMEM);
    cudaFuncSetAttribute(offmask_gemm_kernel,
                         cudaFuncAttributeMaxDynamicSharedMemorySize, OM_SMEM);

    __half *xh, *xl, *qwh, *qwl, *pwh, *pwl, *aoh, *aol;
    float *qkv;
    cudaGetSymbolAddress((void**)&xh, g_xhi);   cudaGetSymbolAddress((void**)&xl, g_xlo);
    cudaGetSymbolAddress((void**)&qwh, g_qwh);  cudaGetSymbolAddress((void**)&qwl, g_qwl);
    cudaGetSymbolAddress((void**)&pwh, g_pwh);  cudaGetSymbolAddress((void**)&pwl, g_pwl);
    cudaGetSymbolAddress((void**)&aoh, g_aoh);  cudaGetSymbolAddress((void**)&aol, g_aol);
    cudaGetSymbolAddress((void**)&qkv, g_qkv);

    convert_w_kernel<<<C3 + CD, 256>>>(qkv_w, proj_w);                     // 1
    {
        dim3 grid(NOP, NF / 128);
        prep_kernel<<<grid, 128>>>(off_pconv_w, off_w, off_b,
                                   mask_pconv_w, mask_w, mask_b);          // 2
    }
    convert_x_kernel<<<(MR * CD) / 1024, 256>>>(x);                        // 3
    {
        dim3 grid(C3 / 64, MR / 128);
        gemm_kernel<<<grid, 256, GEMM_SMEM>>>(xh, xl, qwh, qwl, qkv_b, qkv,
                                              C3, CD, CD);                 // 4 (profiled)
    }
    {
        dim3 grid(WD / 4, HD, BD);
        dwconv_kernel<<<grid, 192>>>(qkv, dw_w, dw_b);                     // 5
    }
    {
        dim3 grid(NOP / 64, MR / 128);
        offmask_gemm_kernel<<<grid, 256, OM_SMEM>>>();                     // 6
    }
    {
        dim3 grid(PD / 8, GD, BD);
        attn_kernel<<<grid, 256>>>();                                      // 7
    }
    {
        dim3 grid(CD / 64, MR / 128);
        gemm_kernel<<<grid, 256, GEMM_SMEM>>>(aoh, aol, pwh, pwl, proj_b, out,
                                              CD, CD, 0);                  // 8
    }
}

// round 13
// speedup vs baseline: 1.1357x; 1.0245x over previous
#include <cuda_runtime.h>
#include <cuda_fp16.h>
#include <cstdint>

#define BD 2
#define HD 64
#define WD 64
#define CD 256
#define GD 8
#define KP 9
#define HCD 32
#define PD (HD*WD)
#define C3 (3*CD)
#define NOP 192
#define NF 768
#define MR (BD*PD)

// ---------------- scratch ----------------
__device__ float  g_qkv[MR*C3];
__device__ __half g_qh[MR*CD], g_ql[MR*CD];
__device__ float2 g_kv[MR*CD];
__device__ float  g_offmask[MR*NOP];
__device__ float  g_combB[NOP];
__device__ __half g_xhi[MR*CD], g_xlo[MR*CD];
__device__ __half g_qwh[C3*CD], g_qwl[C3*CD];
__device__ __half g_pwh[CD*CD], g_pwl[CD*CD];
__device__ __half g_cwh[NOP*NF], g_cwl[NOP*NF];
__device__ __half g_aoh[MR*CD], g_aol[MR*CD];

__constant__ float c_PTS[18] = {-1,-1,-1,0,-1,1,0,-1,0,0,0,1,1,-1,1,0,1,1};

// ---------------- helpers ----------------
__device__ __forceinline__ uint32_t smem_u32(const void* p) {
    uint32_t a;
    asm("{ .reg .u64 t; cvta.to.shared.u64 t, %1; cvt.u32.u64 %0, t; }" : "=r"(a) : "l"(p));
    return a;
}
__device__ __forceinline__ void cp16(uint32_t dst, const void* src) {
    asm volatile("cp.async.cg.shared.global [%0], [%1], 16;" :: "r"(dst), "l"(src));
}
#define CP_COMMIT() asm volatile("cp.async.commit_group;" ::: "memory")
#define CP_WAIT0()  asm volatile("cp.async.wait_group 0;" ::: "memory")
#define CP_WAIT1()  asm volatile("cp.async.wait_group 1;" ::: "memory")
#define LDSM_X4(r, a) asm volatile( \
    "ldmatrix.sync.aligned.m8n8.x4.shared.b16 {%0,%1,%2,%3}, [%4];" \
    : "=r"((r)[0]),"=r"((r)[1]),"=r"((r)[2]),"=r"((r)[3]) : "r"(a))
#define MMA16816(c, a, b) asm volatile( \
    "mma.sync.aligned.m16n8k16.row.col.f32.f16.f16.f32 " \
    "{%0,%1,%2,%3}, {%4,%5,%6,%7}, {%8,%9}, {%0,%1,%2,%3};" \
    : "+f"((c)[0]),"+f"((c)[1]),"+f"((c)[2]),"+f"((c)[3]) \
    : "r"((a)[0]),"r"((a)[1]),"r"((a)[2]),"r"((a)[3]), "r"((b)[0]),"r"((b)[1]))

__device__ __forceinline__ void split1(float v, __half& hi, __half& lo) {
    hi = __float2half_rn(v);
    lo = __float2half_rn(v - __half2float(hi));
}

// ============ split-fp16 GEMM, 3-stage pipeline, 1 sync/chunk ============
// C[M,N] = A·B^T + bias. Columns < n3 -> 3 products (needs Al), else 2.
// In 2-product tiles Al is neither staged nor ldmatrix'd.
#define AT 5120                        // 128*40 halves per A stage
#define BT 2560                        // 64*40 halves per B stage
#define GEMM_SMEM ((3*AT*2 + 3*BT*2) * 2)   // 92160 bytes

__global__ void __launch_bounds__(256, 2) gemm_kernel(
    const __half* __restrict__ Ah, const __half* __restrict__ Al,
    const __half* __restrict__ Bh, const __half* __restrict__ Bl,
    const float* __restrict__ bias, float* __restrict__ C, int N, int K, int n3)
{
    extern __shared__ __half sm[];
    __half* sAh = sm;                 // [3][128][40]
    __half* sAl = sAh + 3*AT;
    __half* sBh = sAl + 3*AT;         // [3][64][40]
    __half* sBl = sBh + 3*BT;

    int tid = threadIdx.x;
    int warp = tid >> 5, lane = tid & 31;
    int wm = warp >> 1, wn = warp & 1;
    int row0 = blockIdx.y * 128, col0 = blockIdx.x * 64;
    bool full3 = (col0 < n3);

    float acc[2][4][4];
#pragma unroll
    for (int mi = 0; mi < 2; mi++)
#pragma unroll
        for (int j = 0; j < 4; j++)
#pragma unroll
            for (int r = 0; r < 4; r++) acc[mi][j][r] = 0.f;

#define STAGE(kc, s) do { \
    int k0 = (kc) << 5; \
    _Pragma("unroll") \
    for (int i = 0; i < 2; i++) { \
        int e = tid + i * 256; \
        int r = e >> 2, cs = (e & 3) * 8; \
        size_t ga = (size_t)(row0 + r) * K + k0 + cs; \
        cp16(smem_u32(&sAh[(s)*AT + r*40 + cs]), Ah + ga); \
        if (full3) cp16(smem_u32(&sAl[(s)*AT + r*40 + cs]), Al + ga); \
    } \
    { int r = tid >> 2, cs = (tid & 3) * 8; \
      size_t gb = (size_t)(col0 + r) * K + k0 + cs; \
      cp16(smem_u32(&sBh[(s)*BT + r*40 + cs]), Bh + gb); \
      cp16(smem_u32(&sBl[(s)*BT + r*40 + cs]), Bl + gb); } \
} while (0)

    int nk = K >> 5;
    STAGE(0, 0); CP_COMMIT();
    if (nk > 1) { STAGE(1, 1); CP_COMMIT(); }

    int cur = 0, nxt2 = 2;
    for (int kc = 0; kc < nk; kc++) {
        if (kc + 1 < nk) CP_WAIT1(); else CP_WAIT0();
        __syncthreads();
        if (kc + 2 < nk) {
            STAGE(kc + 2, nxt2);
            CP_COMMIT();
            nxt2 = (nxt2 == 2) ? 0 : nxt2 + 1;
        }
        uint32_t aH[2][2][4], aL[2][2][4], bH[2][4][2], bL[2][4][2];
#pragma unroll
        for (int ks = 0; ks < 2; ks++) {
#pragma unroll
            for (int mi = 0; mi < 2; mi++) {
                int rowa = wm * 32 + mi * 16 + (lane & 15);
                int cola = ks * 16 + (lane >> 4) * 8;
                LDSM_X4(aH[ks][mi], smem_u32(&sAh[cur*AT + rowa*40 + cola]));
                if (full3)
                    LDSM_X4(aL[ks][mi], smem_u32(&sAl[cur*AT + rowa*40 + cola]));
            }
#pragma unroll
            for (int jp = 0; jp < 2; jp++) {
                int rowb = wn * 32 + jp * 16 + ((lane >> 4) & 1) * 8 + (lane & 7);
                int colb = ks * 16 + ((lane >> 3) & 1) * 8;
                uint32_t t4[4];
                LDSM_X4(t4, smem_u32(&sBh[cur*BT + rowb*40 + colb]));
                bH[ks][jp*2][0] = t4[0]; bH[ks][jp*2][1] = t4[1];
                bH[ks][jp*2+1][0] = t4[2]; bH[ks][jp*2+1][1] = t4[3];
                LDSM_X4(t4, smem_u32(&sBl[cur*BT + rowb*40 + colb]));
                bL[ks][jp*2][0] = t4[0]; bL[ks][jp*2][1] = t4[1];
                bL[ks][jp*2+1][0] = t4[2]; bL[ks][jp*2+1][1] = t4[3];
            }
        }
#pragma unroll
        for (int ks = 0; ks < 2; ks++) {
#pragma unroll
            for (int mi = 0; mi < 2; mi++)
#pragma unroll
                for (int j = 0; j < 4; j++) {
                    MMA16816(acc[mi][j], aH[ks][mi], bH[ks][j]);
                    MMA16816(acc[mi][j], aH[ks][mi], bL[ks][j]);
                }
            if (full3) {
#pragma unroll
                for (int mi = 0; mi < 2; mi++)
#pragma unroll
                    for (int j = 0; j < 4; j++)
                        MMA16816(acc[mi][j], aL[ks][mi], bH[ks][j]);
            }
        }
        cur = (cur == 2) ? 0 : cur + 1;
    }
#undef STAGE

    int g = lane >> 2, t = lane & 3;
#pragma unroll
    for (int mi = 0; mi < 2; mi++)
#pragma unroll
        for (int j = 0; j < 4; j++) {
            int col = col0 + wn * 32 + j * 8 + t * 2;
            float2 bv = *reinterpret_cast<const float2*>(&bias[col]);
            int r0 = row0 + wm * 32 + mi * 16 + g;
            float2 o0 = make_float2(acc[mi][j][0] + bv.x, acc[mi][j][1] + bv.y);
            float2 o1 = make_float2(acc[mi][j][2] + bv.x, acc[mi][j][3] + bv.y);
            *reinterpret_cast<float2*>(&C[(size_t)r0 * N + col]) = o0;
            *reinterpret_cast<float2*>(&C[(size_t)(r0 + 8) * N + col]) = o1;
        }
}

// ============ fused offset/mask GEMM: double-buffered, reg-staged gather ====
#define OM_SMEM ((2*AT*2 + 2*BT*2) * 2)   // 61440 bytes

__device__ __forceinline__ void om_gather(
    int kc, int b, int hbase, int tid, uint2* hv, uint2* lv)
{
    int f0 = kc << 5;
    int dy, dx, cofs;
    if (f0 < 576) { int t = f0 >> 6; dy = t / 3 - 1; dx = t % 3 - 1; cofs = f0 & 63; }
    else          { dy = 0; dx = 0; cofs = 64 + (f0 - 576); }
#pragma unroll
    for (int i = 0; i < 4; i++) {
        int idx = tid + i * 256;
        int px = idx >> 3;
        int c4 = (idx & 7) << 2;
        int hh = hbase + (px >> 6) + dy;
        int xx = (px & 63) + dx;
        hv[i] = make_uint2(0u, 0u); lv[i] = make_uint2(0u, 0u);
        if (hh >= 0 && hh < HD && xx >= 0 && xx < WD) {
            size_t base = ((size_t)(b * HD + hh) * WD + xx) * CD + cofs + c4;
            hv[i] = *reinterpret_cast<const uint2*>(&g_qh[base]);
            lv[i] = *reinterpret_cast<const uint2*>(&g_ql[base]);
        }
    }
}

__global__ void __launch_bounds__(256, 2) offmask_gemm_kernel()
{
    extern __shared__ __half sm[];
    __half* sAh = sm;
    __half* sAl = sAh + 2*AT;
    __half* sBh = sAl + 2*AT;
    __half* sBl = sBh + 2*BT;

    int tid = threadIdx.x;
    int warp = tid >> 5, lane = tid & 31;
    int wm = warp >> 1, wn = warp & 1;
    int row0 = blockIdx.y * 128, col0 = blockIdx.x * 64;
    int b = row0 >> 12;
    int hbase = (row0 & 4095) >> 6;

    float acc[2][4][4];
#pragma unroll
    for (int mi = 0; mi < 2; mi++)
#pragma unroll
        for (int j = 0; j < 4; j++)
#pragma unroll
            for (int r = 0; r < 4; r++) acc[mi][j][r] = 0.f;

#define OM_STS(s) do { \
    _Pragma("unroll") \
    for (int i = 0; i < 4; i++) { \
        int idx = tid + i * 256; \
        int px = idx >> 3, c4 = (idx & 7) << 2; \
        *reinterpret_cast<uint2*>(&sAh[(s)*AT + px*40 + c4]) = hv[i]; \
        *reinterpret_cast<uint2*>(&sAl[(s)*AT + px*40 + c4]) = lv[i]; \
    } \
} while (0)
#define OM_CPB(kc, s) do { \
    int r = tid >> 2, cs = (tid & 3) * 8; \
    size_t gb = (size_t)(col0 + r) * NF + ((kc) << 5) + cs; \
    cp16(smem_u32(&sBh[(s)*BT + r*40 + cs]), g_cwh + gb); \
    cp16(smem_u32(&sBl[(s)*BT + r*40 + cs]), g_cwl + gb); \
} while (0)

    const int NK = NF / 32;
    uint2 hv[4], lv[4];
    om_gather(0, b, hbase, tid, hv, lv);
    OM_STS(0);
    OM_CPB(0, 0);
    CP_COMMIT();
    om_gather(1, b, hbase, tid, hv, lv);

    for (int kc = 0; kc < NK; kc++) {
        int cur = kc & 1;
        CP_WAIT0();
        __syncthreads();
        if (kc + 1 < NK) {
            OM_STS(cur ^ 1);
            OM_CPB(kc + 1, cur ^ 1);
            CP_COMMIT();
        }
        if (kc + 2 < NK)
            om_gather(kc + 2, b, hbase, tid, hv, lv);

#pragma unroll
        for (int ks = 0; ks < 2; ks++) {
            uint32_t aH[2][4], aL[2][4], bH[4][2], bL[4][2];
#pragma unroll
            for (int mi = 0; mi < 2; mi++) {
                int rowa = wm * 32 + mi * 16 + (lane & 15);
                int cola = ks * 16 + (lane >> 4) * 8;
                LDSM_X4(aH[mi], smem_u32(&sAh[cur*AT + rowa*40 + cola]));
                LDSM_X4(aL[mi], smem_u32(&sAl[cur*AT + rowa*40 + cola]));
            }
#pragma unroll
            for (int jp = 0; jp < 2; jp++) {
                int rowb = wn * 32 + jp * 16 + ((lane >> 4) & 1) * 8 + (lane & 7);
                int colb = ks * 16 + ((lane >> 3) & 1) * 8;
                uint32_t t4[4];
                LDSM_X4(t4, smem_u32(&sBh[cur*BT + rowb*40 + colb]));
                bH[jp*2][0] = t4[0]; bH[jp*2][1] = t4[1];
                bH[jp*2+1][0] = t4[2]; bH[jp*2+1][1] = t4[3];
                LDSM_X4(t4, smem_u32(&sBl[cur*BT + rowb*40 + colb]));
                bL[jp*2][0] = t4[0]; bL[jp*2][1] = t4[1];
                bL[jp*2+1][0] = t4[2]; bL[jp*2+1][1] = t4[3];
            }
#pragma unroll
            for (int mi = 0; mi < 2; mi++)
#pragma unroll
                for (int j = 0; j < 4; j++) {
                    MMA16816(acc[mi][j], aH[mi], bH[j]);
                    MMA16816(acc[mi][j], aH[mi], bL[j]);
                    MMA16816(acc[mi][j], aL[mi], bH[j]);
                }
        }
    }
#undef OM_STS
#undef OM_CPB

    int g = lane >> 2, t = lane & 3;
#pragma unroll
    for (int mi = 0; mi < 2; mi++)
#pragma unroll
        for (int j = 0; j < 4; j++) {
            int col = col0 + wn * 32 + j * 8 + t * 2;
            float2 bv = *reinterpret_cast<const float2*>(&g_combB[col]);
            int r0 = row0 + wm * 32 + mi * 16 + g;
            float2 o0 = make_float2(acc[mi][j][0] + bv.x, acc[mi][j][1] + bv.y);
            float2 o1 = make_float2(acc[mi][j][2] + bv.x, acc[mi][j][3] + bv.y);
            *reinterpret_cast<float2*>(&g_offmask[(size_t)r0 * NOP + col]) = o0;
            *reinterpret_cast<float2*>(&g_offmask[(size_t)(r0 + 8) * NOP + col]) = o1;
        }
}

// ------- merged prep: weight fold + qkv_w/proj_w transpose-split + x split --
// grid: [0, NOP*3)            -> combW fold (o = bid/3, f = (bid%3)*256+tid)
//       [NOP*3, NOP*3+C3+CD)  -> weight transpose split
//       rest (2048 blocks)    -> x split
__global__ void __launch_bounds__(256) allprep_kernel(
    const float* __restrict__ x, const float* __restrict__ qkv_w,
    const float* __restrict__ proj_w,
    const float* __restrict__ off_pconv_w, const float* __restrict__ off_w,
    const float* __restrict__ off_b, const float* __restrict__ mask_pconv_w,
    const float* __restrict__ mask_w, const float* __restrict__ mask_b)
{
    int bid = blockIdx.x, tid = threadIdx.x;
    if (bid < NOP * 3) {
        int o = bid / 3;
        int f = (bid % 3) * 256 + tid;
        if (o >= 153) {
            g_cwh[(size_t)o * NF + f] = __float2half_rn(0.f);
            g_cwl[(size_t)o * NF + f] = __float2half_rn(0.f);
            if (tid == 0 && (bid % 3) == 0) g_combB[o] = 0.f;
            return;
        }
        bool is_mask = (o >= 144);
        int g = 0, j = 0, kk = 0;
        if (!is_mask) { g = o / 18; j = o % 18; } else { kk = o - 144; }
        float s;
        if (f < 576) {
            int t = f >> 6, ic = f & 63;
            s = 0.f;
            if (!is_mask) {
                const float* ow = off_w + (g * 18 + j) * 256;
                const float* pc = off_pconv_w + ((size_t)(g * 64) * 64 + ic) * 9 + t;
#pragma unroll 4
                for (int oc = 0; oc < 64; oc++) s += ow[oc] * pc[(size_t)oc * 64 * 9];
            } else {
                const float* mw = mask_w + kk * 256;
                const float* pc = mask_pconv_w + (size_t)ic * 9 + t;
#pragma unroll 4
                for (int oc = 0; oc < 64; oc++) s += mw[oc] * pc[(size_t)oc * 64 * 9];
            }
        } else {
            int ch = f - 512;
            s = is_mask ? mask_w[kk * 256 + ch] : off_w[(g * 18 + j) * 256 + ch];
        }
        __half h, l; split1(s, h, l);
        g_cwh[(size_t)o * NF + f] = h;
        g_cwl[(size_t)o * NF + f] = l;
        if (tid == 0 && (bid % 3) == 0)
            g_combB[o] = is_mask ? mask_b[kk]
                                 : (off_b[g * 18 + j] + c_PTS[j] * (float)(2 * g + 1));
    } else if (bid < NOP * 3 + C3 + CD) {
        int wb = bid - NOP * 3;
        if (wb < C3) {
            __half h, l; split1(qkv_w[(size_t)tid * C3 + wb], h, l);
            g_qwh[(size_t)wb * CD + tid] = h;
            g_qwl[(size_t)wb * CD + tid] = l;
        } else {
            int o = wb - C3;
            __half h, l; split1(proj_w[(size_t)tid * CD + o], h, l);
            g_pwh[(size_t)o * CD + tid] = h;
            g_pwl[(size_t)o * CD + tid] = l;
        }
    } else {
        int xb = bid - (NOP * 3 + C3 + CD);
        int i = (xb * 256 + tid) * 4;
        float4 v = *reinterpret_cast<const float4*>(&x[i]);
        float f[4] = {v.x, v.y, v.z, v.w};
#pragma unroll
        for (int j = 0; j < 4; j++) {
            __half h, l; split1(f[j], h, l);
            g_xhi[i + j] = h; g_xlo[i + j] = l;
        }
    }
}

// ---------------- depthwise 3x3 ----------------
__global__ void __launch_bounds__(192) dwconv_kernel(
    const float* __restrict__ in, const float* __restrict__ w,
    const float* __restrict__ bias)
{
    int c = threadIdx.x * 4;
    int x0 = blockIdx.x * 4, y = blockIdx.y, b = blockIdx.z;
    float4 bz = *reinterpret_cast<const float4*>(&bias[c]);
    float4 acc[4] = {bz, bz, bz, bz};
#pragma unroll
    for (int ky = 0; ky < 3; ky++) {
        int yy = y + ky - 1;
        if (yy < 0 || yy >= HD) continue;
        const float* rowp = in + ((size_t)(b * HD + yy) * WD) * C3 + c;
        float4 iv[6];
#pragma unroll
        for (int j = 0; j < 6; j++) {
            int xx = x0 - 1 + j;
            iv[j] = (xx >= 0 && xx < WD)
                ? *reinterpret_cast<const float4*>(rowp + (size_t)xx * C3)
                : make_float4(0.f, 0.f, 0.f, 0.f);
        }
#pragma unroll
        for (int kx = 0; kx < 3; kx++) {
            float4 wv = *reinterpret_cast<const float4*>(&w[(ky * 3 + kx) * C3 + c]);
#pragma unroll
            for (int p = 0; p < 4; p++) {
                acc[p].x += wv.x * iv[p + kx].x; acc[p].y += wv.y * iv[p + kx].y;
                acc[p].z += wv.z * iv[p + kx].z; acc[p].w += wv.w * iv[p + kx].w;
            }
        }
    }
#pragma unroll
    for (int p = 0; p < 4; p++) {
        size_t pix = (size_t)(b * HD + y) * WD + x0 + p;
        if (c < CD) {
            __half h0,h1,h2,h3,l0,l1,l2,l3;
            split1(acc[p].x,h0,l0); split1(acc[p].y,h1,l1);
            split1(acc[p].z,h2,l2); split1(acc[p].w,h3,l3);
            size_t o = pix * CD + c;
            *reinterpret_cast<__half2*>(&g_qh[o])   = __halves2half2(h0,h1);
            *reinterpret_cast<__half2*>(&g_qh[o+2]) = __halves2half2(h2,h3);
            *reinterpret_cast<__half2*>(&g_ql[o])   = __halves2half2(l0,l1);
            *reinterpret_cast<__half2*>(&g_ql[o+2]) = __halves2half2(l2,l3);
        } else if (c < 2 * CD) {
            float2* bp = &g_kv[pix * CD + (c - CD)];
            bp[0].x = acc[p].x; bp[1].x = acc[p].y;
            bp[2].x = acc[p].z; bp[3].x = acc[p].w;
        } else {
            float2* bp = &g_kv[pix * CD + (c - 2 * CD)];
            bp[0].y = acc[p].x; bp[1].y = acc[p].y;
            bp[2].y = acc[p].z; bp[3].y = acc[p].w;
        }
    }
}

// ---------------- deformable attention ----------------
__global__ void __launch_bounds__(256) attn_kernel()
{
    int warp = threadIdx.x >> 5, lane = threadIdx.x & 31;
    int px = blockIdx.x * 8 + warp;
    int g = blockIdx.y, b = blockIdx.z;
    int h = px >> 6, w = px & 63;

    const float* om = g_offmask + ((size_t)(b * HD + h) * WD + w) * NOP;
    size_t qi = ((size_t)(b * HD + h) * WD + w) * CD + g * HCD + lane;
    float qv = (__half2float(g_qh[qi]) + __half2float(g_ql[qi]))
             * 0.17677669529663687f;

    float attn[KP], vk[KP];
#pragma unroll
    for (int k = 0; k < KP; k++) {
        float ox = om[g * 18 + 2 * k], oy = om[g * 18 + 2 * k + 1], mk = om[144 + k];
        float cx = fminf(fmaxf((float)w + ox, 0.f), (float)(WD - 1));
        float cy = fminf(fmaxf((float)h + oy, 0.f), (float)(HD - 1));
        float x0f = floorf(cx), y0f = floorf(cy);
        float fx = cx - x0f, fy = cy - y0f;
        int x0 = (int)x0f, y0 = (int)y0f;
        int x1 = min(x0 + 1, WD - 1), y1 = min(y0 + 1, HD - 1);
        size_t i00 = ((size_t)(b * HD + y0) * WD + x0) * CD + g * HCD + lane;
        size_t i01 = ((size_t)(b * HD + y0) * WD + x1) * CD + g * HCD + lane;
        size_t i10 = ((size_t)(b * HD + y1) * WD + x0) * CD + g * HCD + lane;
        size_t i11 = ((size_t)(b * HD + y1) * WD + x1) * CD + g * HCD + lane;
        float2 kv00 = g_kv[i00], kv01 = g_kv[i01];
        float2 kv10 = g_kv[i10], kv11 = g_kv[i11];
        float w00 = (1.f - fx) * (1.f - fy), w01 = fx * (1.f - fy);
        float w10 = (1.f - fx) * fy,         w11 = fx * fy;
        float kvv = kv00.x*w00 + kv01.x*w01 + kv10.x*w10 + kv11.x*w11;
        float vvv = kv00.y*w00 + kv01.y*w01 + kv10.y*w10 + kv11.y*w11;
        kvv *= mk; vvv *= mk;
        float d = qv * kvv;
#pragma unroll
        for (int s = 16; s; s >>= 1) d += __shfl_xor_sync(0xffffffffu, d, s);
        attn[k] = d;
        vk[k] = vvv;
    }
    float m = attn[0];
#pragma unroll
    for (int k = 1; k < KP; k++) m = fmaxf(m, attn[k]);
    float ssum = 0.f, o = 0.f;
#pragma unroll
    for (int k = 0; k < KP; k++) {
        float e = __expf(attn[k] - m);
        ssum += e;
        o += e * vk[k];
    }
    o /= ssum;
    size_t oi = ((size_t)((b * HD + h) * WD + w)) * CD + g * HCD + lane;
    __half hh, ll; split1(o, hh, ll);
    g_aoh[oi] = hh; g_aol[oi] = ll;
}

// --------------------------------- launch ---------------------------------
extern "C" void kernel_launch(void* const* d_in, const int* in_sizes, int n_in,
                              void* d_out, int out_size)
{
    const float* x            = (const float*)d_in[0];
    const float* qkv_w        = (const float*)d_in[1];
    const float* qkv_b        = (const float*)d_in[2];
    const float* dw_w         = (const float*)d_in[3];
    const float* dw_b         = (const float*)d_in[4];
    const float* off_pconv_w  = (const float*)d_in[5];
    const float* off_w        = (const float*)d_in[6];
    const float* off_b        = (const float*)d_in[7];
    const float* mask_pconv_w = (const float*)d_in[8];
    const float* mask_w       = (const float*)d_in[9];
    const float* mask_b       = (const float*)d_in[10];
    const float* proj_w       = (const float*)d_in[11];
    const float* proj_b       = (const float*)d_in[12];
    float* out = (float*)d_out;

    cudaFuncSetAttribute(gemm_kernel,
                         cudaFuncAttributeMaxDynamicSharedMemorySize, GEMM_SMEM);
    cudaFuncSetAttribute(offmask_gemm_kernel,
                         cudaFuncAttributeMaxDynamicSharedMemorySize, OM_SMEM);

    __half *xh, *xl, *qwh, *qwl, *pwh, *pwl, *aoh, *aol;
    float *qkv;
    cudaGetSymbolAddress((void**)&xh, g_xhi);   cudaGetSymbolAddress((void**)&xl, g_xlo);
    cudaGetSymbolAddress((void**)&qwh, g_qwh);  cudaGetSymbolAddress((void**)&qwl, g_qwl);
    cudaGetSymbolAddress((void**)&pwh, g_pwh);  cudaGetSymbolAddress((void**)&pwl, g_pwl);
    cudaGetSymbolAddress((void**)&aoh, g_aoh);  cudaGetSymbolAddress((void**)&aol, g_aol);
    cudaGetSymbolAddress((void**)&qkv, g_qkv);

    // 1) all prep: weight fold + weight splits + x split
    allprep_kernel<<<NOP * 3 + C3 + CD + 2048, 256>>>(
        x, qkv_w, proj_w, off_pconv_w, off_w, off_b,
        mask_pconv_w, mask_w, mask_b);
    // 2) qkv GEMM (q cols full3, kv cols 2-product)
    {
        dim3 grid(C3 / 64, MR / 128);
        gemm_kernel<<<grid, 256, GEMM_SMEM>>>(xh, xl, qwh, qwl, qkv_b, qkv,
                                              C3, CD, CD);
    }
    // 3) depthwise conv
    {
        dim3 grid(WD / 4, HD, BD);
        dwconv_kernel<<<grid, 192>>>(qkv, dw_w, dw_b);
    }
    // 4) fused offset/mask GEMM  (profiled slot)
    {
        dim3 grid(NOP / 64, MR / 128);
        offmask_gemm_kernel<<<grid, 256, OM_SMEM>>>();
    }
    // 5) attention
    {
        dim3 grid(PD / 8, GD, BD);
        attn_kernel<<<grid, 256>>>();
    }
    // 6) proj GEMM (2-product)
    {
        dim3 grid(CD / 64, MR / 128);
        gemm_kernel<<<grid, 256, GEMM_SMEM>>>(aoh, aol, pwh, pwl, proj_b, out,
                                              CD, CD, 0);
    }
}

// round 14
// speedup vs baseline: 1.1892x; 1.0471x over previous
#include <cuda_runtime.h>
#include <cuda_fp16.h>
#include <cstdint>

#define BD 2
#define HD 64
#define WD 64
#define CD 256
#define GD 8
#define KP 9
#define HCD 32
#define PD (HD*WD)
#define C3 (3*CD)
#define NOP 192
#define NF 768
#define MR (BD*PD)

// ---------------- scratch ----------------
__device__ float  g_qkv[MR*C3];
__device__ __half g_qh[MR*CD], g_ql[MR*CD];
__device__ float2 g_kv[MR*CD];
__device__ float  g_offmask[MR*NOP];
__device__ float  g_combB[NOP];
__device__ __half g_xhi[MR*CD], g_xlo[MR*CD];
__device__ __half g_qwh[C3*CD], g_qwl[C3*CD];
__device__ __half g_pwh[CD*CD], g_pwl[CD*CD];
__device__ __half g_cwh[NOP*NF], g_cwl[NOP*NF];
__device__ __half g_aoh[MR*CD], g_aol[MR*CD];

__constant__ float c_PTS[18] = {-1,-1,-1,0,-1,1,0,-1,0,0,0,1,1,-1,1,0,1,1};

// ---------------- helpers ----------------
__device__ __forceinline__ uint32_t smem_u32(const void* p) {
    uint32_t a;
    asm("{ .reg .u64 t; cvta.to.shared.u64 t, %1; cvt.u32.u64 %0, t; }" : "=r"(a) : "l"(p));
    return a;
}
__device__ __forceinline__ void cp16(uint32_t dst, const void* src) {
    asm volatile("cp.async.cg.shared.global [%0], [%1], 16;" :: "r"(dst), "l"(src));
}
#define CP_COMMIT() asm volatile("cp.async.commit_group;" ::: "memory")
#define CP_WAIT0()  asm volatile("cp.async.wait_group 0;" ::: "memory")
#define CP_WAIT1()  asm volatile("cp.async.wait_group 1;" ::: "memory")
#define LDSM_X4(r, a) asm volatile( \
    "ldmatrix.sync.aligned.m8n8.x4.shared.b16 {%0,%1,%2,%3}, [%4];" \
    : "=r"((r)[0]),"=r"((r)[1]),"=r"((r)[2]),"=r"((r)[3]) : "r"(a))
#define MMA16816(c, a, b) asm volatile( \
    "mma.sync.aligned.m16n8k16.row.col.f32.f16.f16.f32 " \
    "{%0,%1,%2,%3}, {%4,%5,%6,%7}, {%8,%9}, {%0,%1,%2,%3};" \
    : "+f"((c)[0]),"+f"((c)[1]),"+f"((c)[2]),"+f"((c)[3]) \
    : "r"((a)[0]),"r"((a)[1]),"r"((a)[2]),"r"((a)[3]), "r"((b)[0]),"r"((b)[1]))

__device__ __forceinline__ void split1(float v, __half& hi, __half& lo) {
    hi = __float2half_rn(v);
    lo = __float2half_rn(v - __half2float(hi));
}

// ============ split-fp16 GEMM, 3-stage pipeline, 1 sync/chunk ============
#define AT 5120
#define BT 2560
#define GEMM_SMEM ((3*AT*2 + 3*BT*2) * 2)   // 92160

__global__ void __launch_bounds__(256, 2) gemm_kernel(
    const __half* __restrict__ Ah, const __half* __restrict__ Al,
    const __half* __restrict__ Bh, const __half* __restrict__ Bl,
    const float* __restrict__ bias, float* __restrict__ C, int N, int K, int n3)
{
    extern __shared__ __half sm[];
    __half* sAh = sm;
    __half* sAl = sAh + 3*AT;
    __half* sBh = sAl + 3*AT;
    __half* sBl = sBh + 3*BT;

    int tid = threadIdx.x;
    int warp = tid >> 5, lane = tid & 31;
    int wm = warp >> 1, wn = warp & 1;
    int row0 = blockIdx.y * 128, col0 = blockIdx.x * 64;
    bool full3 = (col0 < n3);

    float acc[2][4][4];
#pragma unroll
    for (int mi = 0; mi < 2; mi++)
#pragma unroll
        for (int j = 0; j < 4; j++)
#pragma unroll
            for (int r = 0; r < 4; r++) acc[mi][j][r] = 0.f;

#define STAGE(kc, s) do { \
    int k0 = (kc) << 5; \
    _Pragma("unroll") \
    for (int i = 0; i < 2; i++) { \
        int e = tid + i * 256; \
        int r = e >> 2, cs = (e & 3) * 8; \
        size_t ga = (size_t)(row0 + r) * K + k0 + cs; \
        cp16(smem_u32(&sAh[(s)*AT + r*40 + cs]), Ah + ga); \
        if (full3) cp16(smem_u32(&sAl[(s)*AT + r*40 + cs]), Al + ga); \
    } \
    { int r = tid >> 2, cs = (tid & 3) * 8; \
      size_t gb = (size_t)(col0 + r) * K + k0 + cs; \
      cp16(smem_u32(&sBh[(s)*BT + r*40 + cs]), Bh + gb); \
      cp16(smem_u32(&sBl[(s)*BT + r*40 + cs]), Bl + gb); } \
} while (0)

    int nk = K >> 5;
    STAGE(0, 0); CP_COMMIT();
    if (nk > 1) { STAGE(1, 1); CP_COMMIT(); }

    int cur = 0, nxt2 = 2;
    for (int kc = 0; kc < nk; kc++) {
        if (kc + 1 < nk) CP_WAIT1(); else CP_WAIT0();
        __syncthreads();
        if (kc + 2 < nk) {
            STAGE(kc + 2, nxt2);
            CP_COMMIT();
            nxt2 = (nxt2 == 2) ? 0 : nxt2 + 1;
        }
        uint32_t aH[2][2][4], aL[2][2][4], bH[2][4][2], bL[2][4][2];
#pragma unroll
        for (int ks = 0; ks < 2; ks++) {
#pragma unroll
            for (int mi = 0; mi < 2; mi++) {
                int rowa = wm * 32 + mi * 16 + (lane & 15);
                int cola = ks * 16 + (lane >> 4) * 8;
                LDSM_X4(aH[ks][mi], smem_u32(&sAh[cur*AT + rowa*40 + cola]));
                if (full3)
                    LDSM_X4(aL[ks][mi], smem_u32(&sAl[cur*AT + rowa*40 + cola]));
            }
#pragma unroll
            for (int jp = 0; jp < 2; jp++) {
                int rowb = wn * 32 + jp * 16 + ((lane >> 4) & 1) * 8 + (lane & 7);
                int colb = ks * 16 + ((lane >> 3) & 1) * 8;
                uint32_t t4[4];
                LDSM_X4(t4, smem_u32(&sBh[cur*BT + rowb*40 + colb]));
                bH[ks][jp*2][0] = t4[0]; bH[ks][jp*2][1] = t4[1];
                bH[ks][jp*2+1][0] = t4[2]; bH[ks][jp*2+1][1] = t4[3];
                LDSM_X4(t4, smem_u32(&sBl[cur*BT + rowb*40 + colb]));
                bL[ks][jp*2][0] = t4[0]; bL[ks][jp*2][1] = t4[1];
                bL[ks][jp*2+1][0] = t4[2]; bL[ks][jp*2+1][1] = t4[3];
            }
        }
#pragma unroll
        for (int ks = 0; ks < 2; ks++) {
#pragma unroll
            for (int mi = 0; mi < 2; mi++)
#pragma unroll
                for (int j = 0; j < 4; j++) {
                    MMA16816(acc[mi][j], aH[ks][mi], bH[ks][j]);
                    MMA16816(acc[mi][j], aH[ks][mi], bL[ks][j]);
                }
            if (full3) {
#pragma unroll
                for (int mi = 0; mi < 2; mi++)
#pragma unroll
                    for (int j = 0; j < 4; j++)
                        MMA16816(acc[mi][j], aL[ks][mi], bH[ks][j]);
            }
        }
        cur = (cur == 2) ? 0 : cur + 1;
    }
#undef STAGE

    int g = lane >> 2, t = lane & 3;
#pragma unroll
    for (int mi = 0; mi < 2; mi++)
#pragma unroll
        for (int j = 0; j < 4; j++) {
            int col = col0 + wn * 32 + j * 8 + t * 2;
            float2 bv = *reinterpret_cast<const float2*>(&bias[col]);
            int r0 = row0 + wm * 32 + mi * 16 + g;
            float2 o0 = make_float2(acc[mi][j][0] + bv.x, acc[mi][j][1] + bv.y);
            float2 o1 = make_float2(acc[mi][j][2] + bv.x, acc[mi][j][3] + bv.y);
            *reinterpret_cast<float2*>(&C[(size_t)r0 * N + col]) = o0;
            *reinterpret_cast<float2*>(&C[(size_t)(r0 + 8) * N + col]) = o1;
        }
}

// ====== fused offset/mask GEMM: 64x64 tiles, 128 threads, 4 warps ======
// Tile = one image row (64 px). grid (3, 128). Double-buffered; gathers
// register-staged two chunks ahead so LDG latency hides under MMAs.
#define OAT 2560                        // 64*40 halves per A stage
#define OBT 2560                        // 64*40 halves per B stage
#define OM_SMEM ((2*OAT*2 + 2*OBT*2) * 2)   // 40960 bytes

__device__ __forceinline__ void om_gather(
    int kc, int b, int h, int tid, uint2* hv, uint2* lv)
{
    int f0 = kc << 5;
    int dy, dx, cofs;
    if (f0 < 576) { int t = f0 >> 6; dy = t / 3 - 1; dx = t % 3 - 1; cofs = f0 & 63; }
    else          { dy = 0; dx = 0; cofs = 64 + (f0 - 576); }
    int hh = h + dy;
    bool rowok = (hh >= 0 && hh < HD);
    const __half* rh = g_qh + ((size_t)(b * HD + hh) * WD) * CD + cofs;
    const __half* rl = g_ql + ((size_t)(b * HD + hh) * WD) * CD + cofs;
#pragma unroll
    for (int i = 0; i < 4; i++) {
        int idx = tid + i * 128;        // 0..511
        int px = idx >> 3;              // 0..63
        int c4 = (idx & 7) << 2;
        int xx = px + dx;
        hv[i] = make_uint2(0u, 0u); lv[i] = make_uint2(0u, 0u);
        if (rowok && xx >= 0 && xx < WD) {
            size_t base = (size_t)xx * CD + c4;
            hv[i] = *reinterpret_cast<const uint2*>(rh + base);
            lv[i] = *reinterpret_cast<const uint2*>(rl + base);
        }
    }
}

__global__ void __launch_bounds__(128, 4) offmask_gemm_kernel()
{
    extern __shared__ __half sm[];
    __half* sAh = sm;                 // [2][64][40]
    __half* sAl = sAh + 2*OAT;
    __half* sBh = sAl + 2*OAT;        // [2][64][40]
    __half* sBl = sBh + 2*OBT;

    int tid = threadIdx.x;
    int warp = tid >> 5, lane = tid & 31;
    int wm = warp >> 1, wn = warp & 1;
    int row0 = blockIdx.y * 64, col0 = blockIdx.x * 64;
    int b = row0 >> 12;
    int h = (row0 & 4095) >> 6;       // tile = one image row

    float acc[2][4][4];
#pragma unroll
    for (int mi = 0; mi < 2; mi++)
#pragma unroll
        for (int j = 0; j < 4; j++)
#pragma unroll
            for (int r = 0; r < 4; r++) acc[mi][j][r] = 0.f;

#define OM_STS(s) do { \
    _Pragma("unroll") \
    for (int i = 0; i < 4; i++) { \
        int idx = tid + i * 128; \
        int px = idx >> 3, c4 = (idx & 7) << 2; \
        *reinterpret_cast<uint2*>(&sAh[(s)*OAT + px*40 + c4]) = hv[i]; \
        *reinterpret_cast<uint2*>(&sAl[(s)*OAT + px*40 + c4]) = lv[i]; \
    } \
} while (0)
#define OM_CPB(kc, s) do { \
    _Pragma("unroll") \
    for (int i = 0; i < 2; i++) { \
        int e = tid + i * 128; \
        int r = e >> 2, cs = (e & 3) * 8; \
        size_t gb = (size_t)(col0 + r) * NF + ((kc) << 5) + cs; \
        cp16(smem_u32(&sBh[(s)*OBT + r*40 + cs]), g_cwh + gb); \
        cp16(smem_u32(&sBl[(s)*OBT + r*40 + cs]), g_cwl + gb); \
    } \
} while (0)

    const int NK = NF / 32;           // 24
    uint2 hv[4], lv[4];
    om_gather(0, b, h, tid, hv, lv);
    OM_STS(0);
    OM_CPB(0, 0);
    CP_COMMIT();
    om_gather(1, b, h, tid, hv, lv);

    for (int kc = 0; kc < NK; kc++) {
        int cur = kc & 1;
        CP_WAIT0();
        __syncthreads();
        if (kc + 1 < NK) {
            OM_STS(cur ^ 1);
            OM_CPB(kc + 1, cur ^ 1);
            CP_COMMIT();
        }
        if (kc + 2 < NK)
            om_gather(kc + 2, b, h, tid, hv, lv);

#pragma unroll
        for (int ks = 0; ks < 2; ks++) {
            uint32_t aH[2][4], aL[2][4], bH[4][2], bL[4][2];
#pragma unroll
            for (int mi = 0; mi < 2; mi++) {
                int rowa = wm * 32 + mi * 16 + (lane & 15);
                int cola = ks * 16 + (lane >> 4) * 8;
                LDSM_X4(aH[mi], smem_u32(&sAh[cur*OAT + rowa*40 + cola]));
                LDSM_X4(aL[mi], smem_u32(&sAl[cur*OAT + rowa*40 + cola]));
            }
#pragma unroll
            for (int jp = 0; jp < 2; jp++) {
                int rowb = wn * 32 + jp * 16 + ((lane >> 4) & 1) * 8 + (lane & 7);
                int colb = ks * 16 + ((lane >> 3) & 1) * 8;
                uint32_t t4[4];
                LDSM_X4(t4, smem_u32(&sBh[cur*OBT + rowb*40 + colb]));
                bH[jp*2][0] = t4[0]; bH[jp*2][1] = t4[1];
                bH[jp*2+1][0] = t4[2]; bH[jp*2+1][1] = t4[3];
                LDSM_X4(t4, smem_u32(&sBl[cur*OBT + rowb*40 + colb]));
                bL[jp*2][0] = t4[0]; bL[jp*2][1] = t4[1];
                bL[jp*2+1][0] = t4[2]; bL[jp*2+1][1] = t4[3];
            }
#pragma unroll
            for (int mi = 0; mi < 2; mi++)
#pragma unroll
                for (int j = 0; j < 4; j++) {
                    MMA16816(acc[mi][j], aH[mi], bH[j]);
                    MMA16816(acc[mi][j], aH[mi], bL[j]);
                    MMA16816(acc[mi][j], aL[mi], bH[j]);
                }
        }
    }
#undef OM_STS
#undef OM_CPB

    int g = lane >> 2, t = lane & 3;
#pragma unroll
    for (int mi = 0; mi < 2; mi++)
#pragma unroll
        for (int j = 0; j < 4; j++) {
            int col = col0 + wn * 32 + j * 8 + t * 2;
            float2 bv = *reinterpret_cast<const float2*>(&g_combB[col]);
            int r0 = row0 + wm * 32 + mi * 16 + g;
            float2 o0 = make_float2(acc[mi][j][0] + bv.x, acc[mi][j][1] + bv.y);
            float2 o1 = make_float2(acc[mi][j][2] + bv.x, acc[mi][j][3] + bv.y);
            *reinterpret_cast<float2*>(&g_offmask[(size_t)r0 * NOP + col]) = o0;
            *reinterpret_cast<float2*>(&g_offmask[(size_t)(r0 + 8) * NOP + col]) = o1;
        }
}

// ------- merged prep -------
__global__ void __launch_bounds__(256) allprep_kernel(
    const float* __restrict__ x, const float* __restrict__ qkv_w,
    const float* __restrict__ proj_w,
    const float* __restrict__ off_pconv_w, const float* __restrict__ off_w,
    const float* __restrict__ off_b, const float* __restrict__ mask_pconv_w,
    const float* __restrict__ mask_w, const float* __restrict__ mask_b)
{
    int bid = blockIdx.x, tid = threadIdx.x;
    if (bid < NOP * 3) {
        int o = bid / 3;
        int f = (bid % 3) * 256 + tid;
        if (o >= 153) {
            g_cwh[(size_t)o * NF + f] = __float2half_rn(0.f);
            g_cwl[(size_t)o * NF + f] = __float2half_rn(0.f);
            if (tid == 0 && (bid % 3) == 0) g_combB[o] = 0.f;
            return;
        }
        bool is_mask = (o >= 144);
        int g = 0, j = 0, kk = 0;
        if (!is_mask) { g = o / 18; j = o % 18; } else { kk = o - 144; }
        float s;
        if (f < 576) {
            int t = f >> 6, ic = f & 63;
            s = 0.f;
            if (!is_mask) {
                const float* ow = off_w + (g * 18 + j) * 256;
                const float* pc = off_pconv_w + ((size_t)(g * 64) * 64 + ic) * 9 + t;
#pragma unroll 4
                for (int oc = 0; oc < 64; oc++) s += ow[oc] * pc[(size_t)oc * 64 * 9];
            } else {
                const float* mw = mask_w + kk * 256;
                const float* pc = mask_pconv_w + (size_t)ic * 9 + t;
#pragma unroll 4
                for (int oc = 0; oc < 64; oc++) s += mw[oc] * pc[(size_t)oc * 64 * 9];
            }
        } else {
            int ch = f - 512;
            s = is_mask ? mask_w[kk * 256 + ch] : off_w[(g * 18 + j) * 256 + ch];
        }
        __half h, l; split1(s, h, l);
        g_cwh[(size_t)o * NF + f] = h;
        g_cwl[(size_t)o * NF + f] = l;
        if (tid == 0 && (bid % 3) == 0)
            g_combB[o] = is_mask ? mask_b[kk]
                                 : (off_b[g * 18 + j] + c_PTS[j] * (float)(2 * g + 1));
    } else if (bid < NOP * 3 + C3 + CD) {
        int wb = bid - NOP * 3;
        if (wb < C3) {
            __half h, l; split1(qkv_w[(size_t)tid * C3 + wb], h, l);
            g_qwh[(size_t)wb * CD + tid] = h;
            g_qwl[(size_t)wb * CD + tid] = l;
        } else {
            int o = wb - C3;
            __half h, l; split1(proj_w[(size_t)tid * CD + o], h, l);
            g_pwh[(size_t)o * CD + tid] = h;
            g_pwl[(size_t)o * CD + tid] = l;
        }
    } else {
        int xb = bid - (NOP * 3 + C3 + CD);
        int i = (xb * 256 + tid) * 4;
        float4 v = *reinterpret_cast<const float4*>(&x[i]);
        float f[4] = {v.x, v.y, v.z, v.w};
#pragma unroll
        for (int j = 0; j < 4; j++) {
            __half h, l; split1(f[j], h, l);
            g_xhi[i + j] = h; g_xlo[i + j] = l;
        }
    }
}

// ---------------- depthwise 3x3 ----------------
__global__ void __launch_bounds__(192) dwconv_kernel(
    const float* __restrict__ in, const float* __restrict__ w,
    const float* __restrict__ bias)
{
    int c = threadIdx.x * 4;
    int x0 = blockIdx.x * 4, y = blockIdx.y, b = blockIdx.z;
    float4 bz = *reinterpret_cast<const float4*>(&bias[c]);
    float4 acc[4] = {bz, bz, bz, bz};
#pragma unroll
    for (int ky = 0; ky < 3; ky++) {
        int yy = y + ky - 1;
        if (yy < 0 || yy >= HD) continue;
        const float* rowp = in + ((size_t)(b * HD + yy) * WD) * C3 + c;
        float4 iv[6];
#pragma unroll
        for (int j = 0; j < 6; j++) {
            int xx = x0 - 1 + j;
            iv[j] = (xx >= 0 && xx < WD)
                ? *reinterpret_cast<const float4*>(rowp + (size_t)xx * C3)
                : make_float4(0.f, 0.f, 0.f, 0.f);
        }
#pragma unroll
        for (int kx = 0; kx < 3; kx++) {
            float4 wv = *reinterpret_cast<const float4*>(&w[(ky * 3 + kx) * C3 + c]);
#pragma unroll
            for (int p = 0; p < 4; p++) {
                acc[p].x += wv.x * iv[p + kx].x; acc[p].y += wv.y * iv[p + kx].y;
                acc[p].z += wv.z * iv[p + kx].z; acc[p].w += wv.w * iv[p + kx].w;
            }
        }
    }
#pragma unroll
    for (int p = 0; p < 4; p++) {
        size_t pix = (size_t)(b * HD + y) * WD + x0 + p;
        if (c < CD) {
            __half h0,h1,h2,h3,l0,l1,l2,l3;
            split1(acc[p].x,h0,l0); split1(acc[p].y,h1,l1);
            split1(acc[p].z,h2,l2); split1(acc[p].w,h3,l3);
            size_t o = pix * CD + c;
            *reinterpret_cast<__half2*>(&g_qh[o])   = __halves2half2(h0,h1);
            *reinterpret_cast<__half2*>(&g_qh[o+2]) = __halves2half2(h2,h3);
            *reinterpret_cast<__half2*>(&g_ql[o])   = __halves2half2(l0,l1);
            *reinterpret_cast<__half2*>(&g_ql[o+2]) = __halves2half2(l2,l3);
        } else if (c < 2 * CD) {
            float2* bp = &g_kv[pix * CD + (c - CD)];
            bp[0].x = acc[p].x; bp[1].x = acc[p].y;
            bp[2].x = acc[p].z; bp[3].x = acc[p].w;
        } else {
            float2* bp = &g_kv[pix * CD + (c - 2 * CD)];
            bp[0].y = acc[p].x; bp[1].y = acc[p].y;
            bp[2].y = acc[p].z; bp[3].y = acc[p].w;
        }
    }
}

// ---------------- deformable attention ----------------
__global__ void __launch_bounds__(256) attn_kernel()
{
    int warp = threadIdx.x >> 5, lane = threadIdx.x & 31;
    int px = blockIdx.x * 8 + warp;
    int g = blockIdx.y, b = blockIdx.z;
    int h = px >> 6, w = px & 63;

    const float* om = g_offmask + ((size_t)(b * HD + h) * WD + w) * NOP;
    size_t qi = ((size_t)(b * HD + h) * WD + w) * CD + g * HCD + lane;
    float qv = (__half2float(g_qh[qi]) + __half2float(g_ql[qi]))
             * 0.17677669529663687f;

    float attn[KP], vk[KP];
#pragma unroll
    for (int k = 0; k < KP; k++) {
        float ox = om[g * 18 + 2 * k], oy = om[g * 18 + 2 * k + 1], mk = om[144 + k];
        float cx = fminf(fmaxf((float)w + ox, 0.f), (float)(WD - 1));
        float cy = fminf(fmaxf((float)h + oy, 0.f), (float)(HD - 1));
        float x0f = floorf(cx), y0f = floorf(cy);
        float fx = cx - x0f, fy = cy - y0f;
        int x0 = (int)x0f, y0 = (int)y0f;
        int x1 = min(x0 + 1, WD - 1), y1 = min(y0 + 1, HD - 1);
        size_t i00 = ((size_t)(b * HD + y0) * WD + x0) * CD + g * HCD + lane;
        size_t i01 = ((size_t)(b * HD + y0) * WD + x1) * CD + g * HCD + lane;
        size_t i10 = ((size_t)(b * HD + y1) * WD + x0) * CD + g * HCD + lane;
        size_t i11 = ((size_t)(b * HD + y1) * WD + x1) * CD + g * HCD + lane;
        float2 kv00 = g_kv[i00], kv01 = g_kv[i01];
        float2 kv10 = g_kv[i10], kv11 = g_kv[i11];
        float w00 = (1.f - fx) * (1.f - fy), w01 = fx * (1.f - fy);
        float w10 = (1.f - fx) * fy,         w11 = fx * fy;
        float kvv = kv00.x*w00 + kv01.x*w01 + kv10.x*w10 + kv11.x*w11;
        float vvv = kv00.y*w00 + kv01.y*w01 + kv10.y*w10 + kv11.y*w11;
        kvv *= mk; vvv *= mk;
        float d = qv * kvv;
#pragma unroll
        for (int s = 16; s; s >>= 1) d += __shfl_xor_sync(0xffffffffu, d, s);
        attn[k] = d;
        vk[k] = vvv;
    }
    float m = attn[0];
#pragma unroll
    for (int k = 1; k < KP; k++) m = fmaxf(m, attn[k]);
    float ssum = 0.f, o = 0.f;
#pragma unroll
    for (int k = 0; k < KP; k++) {
        float e = __expf(attn[k] - m);
        ssum += e;
        o += e * vk[k];
    }
    o /= ssum;
    size_t oi = ((size_t)((b * HD + h) * WD + w)) * CD + g * HCD + lane;
    __half hh, ll; split1(o, hh, ll);
    g_aoh[oi] = hh; g_aol[oi] = ll;
}

// --------------------------------- launch ---------------------------------
extern "C" void kernel_launch(void* const* d_in, const int* in_sizes, int n_in,
                              void* d_out, int out_size)
{
    const float* x            = (const float*)d_in[0];
    const float* qkv_w        = (const float*)d_in[1];
    const float* qkv_b        = (const float*)d_in[2];
    const float* dw_w         = (const float*)d_in[3];
    const float* dw_b         = (const float*)d_in[4];
    const float* off_pconv_w  = (const float*)d_in[5];
    const float* off_w        = (const float*)d_in[6];
    const float* off_b        = (const float*)d_in[7];
    const float* mask_pconv_w = (const float*)d_in[8];
    const float* mask_w       = (const float*)d_in[9];
    const float* mask_b       = (const float*)d_in[10];
    const float* proj_w       = (const float*)d_in[11];
    const float* proj_b       = (const float*)d_in[12];
    float* out = (float*)d_out;

    cudaFuncSetAttribute(gemm_kernel,
                         cudaFuncAttributeMaxDynamicSharedMemorySize, GEMM_SMEM);
    cudaFuncSetAttribute(offmask_gemm_kernel,
                         cudaFuncAttributeMaxDynamicSharedMemorySize, OM_SMEM);

    __half *xh, *xl, *qwh, *qwl, *pwh, *pwl, *aoh, *aol;
    float *qkv;
    cudaGetSymbolAddress((void**)&xh, g_xhi);   cudaGetSymbolAddress((void**)&xl, g_xlo);
    cudaGetSymbolAddress((void**)&qwh, g_qwh);  cudaGetSymbolAddress((void**)&qwl, g_qwl);
    cudaGetSymbolAddress((void**)&pwh, g_pwh);  cudaGetSymbolAddress((void**)&pwl, g_pwl);
    cudaGetSymbolAddress((void**)&aoh, g_aoh);  cudaGetSymbolAddress((void**)&aol, g_aol);
    cudaGetSymbolAddress((void**)&qkv, g_qkv);

    allprep_kernel<<<NOP * 3 + C3 + CD + 2048, 256>>>(
        x, qkv_w, proj_w, off_pconv_w, off_w, off_b,
        mask_pconv_w, mask_w, mask_b);
    {
        dim3 grid(C3 / 64, MR / 128);
        gemm_kernel<<<grid, 256, GEMM_SMEM>>>(xh, xl, qwh, qwl, qkv_b, qkv,
                                              C3, CD, CD);
    }
    {
        dim3 grid(WD / 4, HD, BD);
        dwconv_kernel<<<grid, 192>>>(qkv, dw_w, dw_b);
    }
    {
        dim3 grid(NOP / 64, MR / 64);
        offmask_gemm_kernel<<<grid, 128, OM_SMEM>>>();     // profiled slot
    }
    {
        dim3 grid(PD / 8, GD, BD);
        attn_kernel<<<grid, 256>>>();
    }
    {
        dim3 grid(CD / 64, MR / 128);
        gemm_kernel<<<grid, 256, GEMM_SMEM>>>(aoh, aol, pwh, pwl, proj_b, out,
                                              CD, CD, 0);
    }
}